// round 14
// baseline (speedup 1.0000x reference)
#include <cuda_runtime.h>
#include <cuda_fp16.h>

#define VN 100000
#define EN 1600000
#define BATCH 4
#define BN_EPS 1e-5f
#define NB_SCAN 98            // ceil(VN/1024)
#define G_HIST 6250           // (EN+255)/256
#define G_RS   391            // (VN+255)/256
#define G_STAT 2048           // 32 channels x 64 blocks
#define G_FILL 6250
#define G_APPL 1563           // (VN+63)/64
#define G_ZDEG 391

// ---------------- static device scratch (no allocations allowed) ----------------
// feature tensors fp16, layout (V, C, B): element (v,c,b) at ((v*C+c)*4+b)
__device__ __align__(256) __half g_XN[VN * 32 * BATCH];   // BN'ed input (x0 of layer 0)
__device__ __align__(256) __half g_R1[VN * 64 * BATCH];   // relu(H1) / b2
__device__ __align__(256) __half g_SA[VN * 64 * BATCH];   // x1 / y0^
__device__ __align__(256) __half g_SB[VN * 64 * BATCH];   // x2 / y1^
__device__ __align__(256) __half g_SC[VN * 64 * BATCH];   // x3 / y2^ / b1
__device__ __align__(256) __half g_R0[VN * 64 * BATCH];   // relu(H0) / y3^
__device__ float g_red[128];
__device__ float g_scale[64];
__device__ float g_shift[64];

// folded weights / constant vectors
__device__ float g_wf[4 * 64 * 64];
__device__ float g_bf[64];
__device__ float g_wf2[4 * 64 * 32];
__device__ float g_qb2[32], g_pb2[32], g_qb1[32], g_qout[32];

// CSR scratch
__device__ __align__(256) int   g_deg[VN];
__device__ __align__(256) int   g_rowptr[VN + 1];
__device__ __align__(256) int   g_cursor[VN];
__device__ __align__(256) float g_rowsum[VN];
__device__ __align__(256) int   g_ecol[EN];
__device__ __align__(256) float g_eval[EN];

// decoupled-lookback scan state
__device__ volatile int g_agg[NB_SCAN];
__device__ volatile int g_incl[NB_SCAN];
__device__ volatile int g_flag[NB_SCAN];

// ---------------- fp16 helpers (8 values = 2 channels x 4 batch) ----------------
__device__ __forceinline__ void fma8(float* acc, float w, uint4 q) {
    half2* h = (half2*)&q;
#pragma unroll
    for (int t = 0; t < 4; t++) {
        float2 f = __half22float2(h[t]);
        acc[2 * t]     += w * f.x;
        acc[2 * t + 1] += w * f.y;
    }
}
__device__ __forceinline__ void unpack8(float* z, uint4 q) {
    half2* h = (half2*)&q;
#pragma unroll
    for (int t = 0; t < 4; t++) {
        float2 f = __half22float2(h[t]);
        z[2 * t] = f.x; z[2 * t + 1] = f.y;
    }
}
__device__ __forceinline__ uint4 pack8(const float* r) {
    uint4 q;
    half2* h = (half2*)&q;
#pragma unroll
    for (int t = 0; t < 4; t++) h[t] = __floats2half2_rn(r[2 * t], r[2 * t + 1]);
    return q;
}

// ================= launch 1: edge histogram + input BN stats + zero rowsum =================
__global__ void __launch_bounds__(256) k_hist_stats(const int* __restrict__ rows,
                                                    const float* __restrict__ x) {
    int b = blockIdx.x;
    if (b < G_HIST) {
        int e = b * 256 + threadIdx.x;
        if (e < EN) atomicAdd(&g_deg[rows[e]], 1);
        return;
    }
    b -= G_HIST;
    if (b < G_RS) {
        int i = b * 256 + threadIdx.x;
        if (i < VN) g_rowsum[i] = 0.f;
        return;
    }
    b -= G_RS;
    int c = b >> 6;
    int chunk = b & 63;
    float s1 = 0.f, s2 = 0.f;
    for (int v = chunk * 256 + threadIdx.x; v < VN; v += 64 * 256) {
#pragma unroll
        for (int bb = 0; bb < BATCH; bb++) {
            float t = x[(bb * 32 + c) * VN + v];
            s1 += t; s2 += t * t;
        }
    }
    __shared__ float sh1[256], sh2[256];
    sh1[threadIdx.x] = s1; sh2[threadIdx.x] = s2;
    __syncthreads();
    for (int off = 128; off > 0; off >>= 1) {
        if (threadIdx.x < off) {
            sh1[threadIdx.x] += sh1[threadIdx.x + off];
            sh2[threadIdx.x] += sh2[threadIdx.x + off];
        }
        __syncthreads();
    }
    if (threadIdx.x == 0) {
        atomicAdd(&g_red[c], sh1[0]);
        atomicAdd(&g_red[64 + c], sh2[0]);
    }
}

// ================= launch 2: decoupled-lookback scan + input BN finalize =================
__global__ void __launch_bounds__(1024) k_scan() {
    int b = blockIdx.x;
    int t = threadIdx.x;
    if (b == NB_SCAN) {
        __shared__ float sm[32], sv[32];
        if (t < 32) {
            float n = (float)VN * (float)BATCH;
            float m = g_red[t] / n;
            float var = g_red[64 + t] / n - m * m;
            sm[t] = m;
            sv[t] = rsqrtf(var + BN_EPS);
        }
        __syncthreads();
        if (t < 32) {
            g_scale[t] = sv[t];   // raw inv-std
            g_shift[t] = sm[t];   // raw mean
        }
        if (t < 128) g_red[t] = 0.f;
        if (t == 0) g_rowptr[VN] = EN;
        return;
    }
    __shared__ int sh[1024];
    int i = b * 1024 + t;
    int val = (i < VN) ? g_deg[i] : 0;
    sh[t] = val;
    __syncthreads();
    for (int off = 1; off < 1024; off <<= 1) {
        int tmp = (t >= off) ? sh[t - off] : 0;
        __syncthreads();
        sh[t] += tmp;
        __syncthreads();
    }
    __shared__ int s_prefix;
    if (t == 0) {
        int total = sh[1023];
        int prefix = 0;
        if (b == 0) {
            g_incl[0] = total;
            __threadfence();
            g_flag[0] = 2;
        } else {
            g_agg[b] = total;
            __threadfence();
            g_flag[b] = 1;
            int j = b - 1;
            while (true) {
                int f;
                while ((f = g_flag[j]) == 0) { }
                if (f == 2) { prefix += g_incl[j]; break; }
                prefix += g_agg[j];
                j--;
            }
            g_incl[b] = prefix + total;
            __threadfence();
            g_flag[b] = 2;
        }
        s_prefix = prefix;
    }
    __syncthreads();
    if (i < VN) {
        int excl = s_prefix + sh[t] - val;
        g_rowptr[i] = excl;
        g_cursor[i] = excl;
    }
}

// ================= launch 3: CSR fill + input BN apply/transpose + zero deg/flags =========
__global__ void __launch_bounds__(256) k_fill_apply(
        const int* __restrict__ rows, const int* __restrict__ cols,
        const float* __restrict__ vals, const float* __restrict__ x,
        const float* __restrict__ gam, const float* __restrict__ bet,
        uint2* __restrict__ xn) {
    int b = blockIdx.x;
    if (b < G_FILL) {
        int e = b * 256 + threadIdx.x;
        if (e < EN) {
            int r = rows[e];
            float w = vals[e];
            int pos = atomicAdd(&g_cursor[r], 1);
            g_ecol[pos] = cols[e];
            g_eval[pos] = w;
            atomicAdd(&g_rowsum[r], w);
        }
        return;
    }
    b -= G_FILL;
    if (b < G_APPL) {
        __shared__ uint2 tile[64 * 33];
        __shared__ float ssc[32], ssf[32];
        if (threadIdx.x < 32) {
            int c = threadIdx.x;
            float sc = gam[c] * g_scale[c];
            ssc[c] = sc;
            ssf[c] = bet[c] - g_shift[c] * sc;
        }
        __syncthreads();
        int v0 = b * 64;
        for (int i = threadIdx.x; i < 32 * 64; i += 256) {
            int c = i >> 6, vi = i & 63;
            int v = v0 + vi;
            uint2 q = make_uint2(0u, 0u);
            if (v < VN) {
                float sc = ssc[c], sf = ssf[c];
                float r0 = sc * x[(0 * 32 + c) * VN + v] + sf;
                float r1 = sc * x[(1 * 32 + c) * VN + v] + sf;
                float r2 = sc * x[(2 * 32 + c) * VN + v] + sf;
                float r3 = sc * x[(3 * 32 + c) * VN + v] + sf;
                half2* h = (half2*)&q;
                h[0] = __floats2half2_rn(r0, r1);
                h[1] = __floats2half2_rn(r2, r3);
            }
            tile[vi * 33 + c] = q;
        }
        __syncthreads();
        for (int i = threadIdx.x; i < 32 * 64; i += 256) {
            int vi = i >> 5, c = i & 31;
            int v = v0 + vi;
            if (v < VN) xn[v * 32 + c] = tile[vi * 33 + c];
        }
        return;
    }
    b -= G_APPL;
    int i = b * 256 + threadIdx.x;
    if (i < VN) g_deg[i] = 0;
    if (b == 0 && threadIdx.x < NB_SCAN) g_flag[threadIdx.x] = 0;
}

// ---------------- fused hidden-BN finalize + layer-1 weight fold (race-fixed) ---------------
__global__ void __launch_bounds__(1024) k_bn_fold1(
        const float* __restrict__ gam, const float* __restrict__ bet,
        const float* __restrict__ w, const float* __restrict__ bias) {
    int t = threadIdx.x;
    __shared__ float ssc[64], ssf[64];
    if (t < 64) {
        float n = (float)VN * (float)BATCH;
        float m = g_red[t] / n;
        float var = g_red[64 + t] / n - m * m;
        float sc = gam[t] * rsqrtf(var + BN_EPS);
        ssc[t] = sc;
        ssf[t] = bet[t] - m * sc;
    }
    __syncthreads();
    if (t < 64) { g_scale[t] = ssc[t]; g_shift[t] = ssf[t]; }
    if (t < 128) g_red[t] = 0.f;
    for (int i = t; i < 16384; i += 1024) {
        int k = i >> 12;
        int c = (i >> 6) & 63;
        float wv = w[i];
        g_wf[i] = (k == 0) ? wv * ssc[c] : wv;
    }
    if (t < 64) {
        float s = bias[t];
        for (int c = 0; c < 64; c++) s += w[c * 64 + t] * ssf[c];
        g_bf[t] = s;
    }
}

// ---------------- fused hidden-BN finalize + layer-2 weight fold + Clenshaw consts ---------
__global__ void __launch_bounds__(1024) k_bn_fold2(
        const float* __restrict__ gam, const float* __restrict__ bet,
        const float* __restrict__ w) {
    int t = threadIdx.x;
    __shared__ float ssc[64], ssf[64];
    __shared__ float su[4 * 32];
    if (t < 64) {
        float n = (float)VN * (float)BATCH;
        float m = g_red[t] / n;
        float var = g_red[64 + t] / n - m * m;
        float sc = gam[t] * rsqrtf(var + BN_EPS);
        ssc[t] = sc;
        ssf[t] = bet[t] - m * sc;
    }
    __syncthreads();
    if (t < 64) { g_scale[t] = ssc[t]; g_shift[t] = ssf[t]; }
    if (t < 128) g_red[t] = 0.f;
    for (int i = t; i < 8192; i += 1024) {
        int c = (i >> 5) & 63;
        g_wf2[i] = w[i] * ssc[c];
    }
    if (t < 128) {
        int k = t >> 5, o = t & 31;
        float u = 0.f;
        for (int c = 0; c < 64; c++) u += w[k * 2048 + c * 32 + o] * ssf[c];
        su[t] = u;
    }
    __syncthreads();
    if (t < 32) {
        g_qb2[t]  = su[2 * 32 + t];
        g_pb2[t]  = 2.f * su[3 * 32 + t];
        g_qb1[t]  = su[1 * 32 + t] - su[3 * 32 + t];
        g_qout[t] = su[0 * 32 + t];
    }
}

// ---------------- gather SpMM, fp16, RU4 lanes per vertex; 8 blocks/SM target --------------
template<int RU4, bool AFFX, bool HASZ1, bool AFFZ1, bool HASZ2, bool HASP, bool HASQ, bool FINAL>
__global__ void __launch_bounds__(256, 8) k_gather(
        float coef, const uint4* __restrict__ X,
        const uint4* __restrict__ Z1, float s1,
        const uint4* __restrict__ Z2, float s2,
        uint4* __restrict__ Y,
        const float* __restrict__ qv, const float* __restrict__ pv,
        const float* __restrict__ bias, const uint4* __restrict__ xn,
        float* __restrict__ outF) {
    const int VPB = 256 / RU4;
    int vs = threadIdx.x / RU4;
    int j  = threadIdx.x % RU4;
    int v  = blockIdx.x * VPB + vs;

    float r[8] = {0.f, 0.f, 0.f, 0.f, 0.f, 0.f, 0.f, 0.f};
    if (v < VN) {
        int s = g_rowptr[v];
        int e = g_rowptr[v + 1];
        float acc[8] = {0.f, 0.f, 0.f, 0.f, 0.f, 0.f, 0.f, 0.f};
        int i = s;
        for (; i < e && (i & 3); i++) {
            fma8(acc, __ldcs(&g_eval[i]), X[__ldcs(&g_ecol[i]) * RU4 + j]);
        }
        for (; i + 8 <= e; i += 8) {
            int4   ca = __ldcs((const int4*)&g_ecol[i]);
            int4   cb = __ldcs((const int4*)&g_ecol[i + 4]);
            float4 wa = __ldcs((const float4*)&g_eval[i]);
            float4 wb = __ldcs((const float4*)&g_eval[i + 4]);
            uint4 q0 = X[ca.x * RU4 + j];
            uint4 q1 = X[ca.y * RU4 + j];
            uint4 q2 = X[ca.z * RU4 + j];
            uint4 q3 = X[ca.w * RU4 + j];
            uint4 q4 = X[cb.x * RU4 + j];
            uint4 q5 = X[cb.y * RU4 + j];
            uint4 q6 = X[cb.z * RU4 + j];
            uint4 q7 = X[cb.w * RU4 + j];
            fma8(acc, wa.x, q0);
            fma8(acc, wa.y, q1);
            fma8(acc, wa.z, q2);
            fma8(acc, wa.w, q3);
            fma8(acc, wb.x, q4);
            fma8(acc, wb.y, q5);
            fma8(acc, wb.z, q6);
            fma8(acc, wb.w, q7);
        }
        for (; i + 4 <= e; i += 4) {
            int4   cc = __ldcs((const int4*)&g_ecol[i]);
            float4 ww = __ldcs((const float4*)&g_eval[i]);
            uint4 q0 = X[cc.x * RU4 + j];
            uint4 q1 = X[cc.y * RU4 + j];
            uint4 q2 = X[cc.z * RU4 + j];
            uint4 q3 = X[cc.w * RU4 + j];
            fma8(acc, ww.x, q0);
            fma8(acc, ww.y, q1);
            fma8(acc, ww.z, q2);
            fma8(acc, ww.w, q3);
        }
        for (; i < e; i++) {
            fma8(acc, __ldcs(&g_eval[i]), X[__ldcs(&g_ecol[i]) * RU4 + j]);
        }

        float sc0, sc1, sf0, sf1, rs = 0.f;
        if (AFFX || AFFZ1) {
            sc0 = g_scale[2 * j]; sc1 = g_scale[2 * j + 1];
            sf0 = g_shift[2 * j]; sf1 = g_shift[2 * j + 1];
        }
        if (AFFX || HASP) rs = g_rowsum[v];

        if (AFFX) {
#pragma unroll
            for (int b = 0; b < 4; b++) {
                r[b]     = coef * (sc0 * acc[b]     + sf0 * rs);
                r[4 + b] = coef * (sc1 * acc[4 + b] + sf1 * rs);
            }
        } else {
#pragma unroll
            for (int t = 0; t < 8; t++) r[t] = coef * acc[t];
        }
        if (HASZ1) {
            float z[8];
            unpack8(z, __ldcs(&Z1[v * RU4 + j]));
            if (AFFZ1) {
#pragma unroll
                for (int b = 0; b < 4; b++) {
                    r[b]     += s1 * (sc0 * z[b]     + sf0);
                    r[4 + b] += s1 * (sc1 * z[4 + b] + sf1);
                }
            } else {
#pragma unroll
                for (int t = 0; t < 8; t++) r[t] += s1 * z[t];
            }
        }
        if (HASZ2) {
            float z[8];
            unpack8(z, __ldcs(&Z2[v * RU4 + j]));
#pragma unroll
            for (int t = 0; t < 8; t++) r[t] += s2 * z[t];
        }
        if (HASQ) {
            float q0 = qv[2 * j], q1 = qv[2 * j + 1];
#pragma unroll
            for (int b = 0; b < 4; b++) { r[b] += q0; r[4 + b] += q1; }
        }
        if (HASP) {
            float p0 = pv[2 * j], p1 = pv[2 * j + 1];
#pragma unroll
            for (int b = 0; b < 4; b++) { r[b] += rs * p0; r[4 + b] += rs * p1; }
        }
        if (!FINAL) {
            __stcs(&Y[v * RU4 + j], pack8(r));
        }
    }

    if (FINAL) {
        // RU4 == 16, VPB == 16
        __shared__ float tile[16 * 32 * 4];
        if (v < VN) {
            float xr[8];
            unpack8(xr, xn[v * 16 + j]);
            float b0 = bias[2 * j], b1 = bias[2 * j + 1];
#pragma unroll
            for (int b = 0; b < 4; b++) {
                r[b]     = fmaxf(r[b]     + b0 + xr[b],     0.f);
                r[4 + b] = fmaxf(r[4 + b] + b1 + xr[4 + b], 0.f);
            }
        } else {
#pragma unroll
            for (int t = 0; t < 8; t++) r[t] = 0.f;
        }
#pragma unroll
        for (int b = 0; b < 4; b++) {
            tile[(vs * 32 + 2 * j) * 4 + b]     = r[b];
            tile[(vs * 32 + 2 * j + 1) * 4 + b] = r[4 + b];
        }
        __syncthreads();
        int vl = threadIdx.x & 15;
        int cw = threadIdx.x >> 4;
        int vv = blockIdx.x * 16 + vl;
        if (vv < VN) {
#pragma unroll
            for (int ci = 0; ci < 2; ci++) {
                int c = cw + ci * 16;
#pragma unroll
                for (int b = 0; b < 4; b++) {
                    outF[(b * 32 + c) * VN + vv] = tile[(vl * 32 + c) * 4 + b];
                }
            }
        }
    }
}

// ---------------- combine (R9 form): fp16 smem, scalar FFMA; BN stats fused ----------------
template<int C, int O, int ITER>
__global__ void __launch_bounds__(256) k_combine(
        const uint4* __restrict__ x0, const uint4* __restrict__ x1,
        const uint4* __restrict__ x2, const uint4* __restrict__ x3,
        const float* __restrict__ w, const float* __restrict__ bias,
        uint2* __restrict__ outR) {
    const int KC = 4 * C;
    const int RU = C / 2;
    const int VPB = 256 / O;
    extern __shared__ char smem[];
    float* sW = (float*)smem;
    uint4* sX = (uint4*)(smem + (size_t)KC * O * sizeof(float));
    __shared__ float sS1[64], sS2[64];
    const int tid = threadIdx.x;

    if (tid < O) { sS1[tid] = 0.f; sS2[tid] = 0.f; }
    for (int i = tid; i < KC * O; i += 256) sW[i] = w[i];

    const int o = tid % O;
    const int vs = tid / O;
    const float bb = bias[o];
    float ls1 = 0.f, ls2 = 0.f;

    for (int it = 0; it < ITER; it++) {
        const int v0 = (blockIdx.x * ITER + it) * VPB;
        __syncthreads();
        for (int i = tid; i < VPB * 4 * RU; i += 256) {
            int vsl = i / (4 * RU);
            int rem = i - vsl * (4 * RU);
            int k = rem / RU, u = rem - k * RU;
            int v = v0 + vsl;
            const uint4* src = (k == 0) ? x0 : (k == 1) ? x1 : (k == 2) ? x2 : x3;
            sX[i] = (v < VN) ? src[v * RU + u] : make_uint4(0u, 0u, 0u, 0u);
        }
        __syncthreads();

        int v = v0 + vs;
        if (v < VN) {
            float4 acc = make_float4(bb, bb, bb, bb);
            const half2* xh = (const half2*)(sX + vs * 4 * RU);
#pragma unroll 8
            for (int kc = 0; kc < KC; kc++) {
                float wv = sW[kc * O + o];
                float2 a = __half22float2(xh[2 * kc]);
                float2 b = __half22float2(xh[2 * kc + 1]);
                acc.x += wv * a.x; acc.y += wv * a.y;
                acc.z += wv * b.x; acc.w += wv * b.y;
            }
            float a = fmaxf(acc.x, 0.f), b = fmaxf(acc.y, 0.f);
            float d = fmaxf(acc.z, 0.f), f = fmaxf(acc.w, 0.f);
            uint2 q;
            half2* h = (half2*)&q;
            h[0] = __floats2half2_rn(a, b);
            h[1] = __floats2half2_rn(d, f);
            outR[v * O + o] = q;
            ls1 += a + b + d + f;
            ls2 += a * a + b * b + d * d + f * f;
        }
    }

    atomicAdd(&sS1[o], ls1);
    atomicAdd(&sS2[o], ls2);
    __syncthreads();
    if (tid < O) {
        atomicAdd(&g_red[tid], sS1[tid]);
        atomicAdd(&g_red[64 + tid], sS2[tid]);
    }
}

// ---------------- combine4 (R9 form): y^_k = wf2_k^T R1, fp16 ----------------
template<int ITER>
__global__ void __launch_bounds__(256) k_combine4(
        const uint4* __restrict__ x, const float* __restrict__ w,
        uint2* __restrict__ y0, uint2* __restrict__ y1,
        uint2* __restrict__ y2, uint2* __restrict__ y3) {
    __shared__ float sW[4 * 64 * 32];
    __shared__ uint4 sX[2 * 32];
    const int tid = threadIdx.x;

    for (int i = tid; i < 4 * 64 * 32; i += 256) sW[i] = w[i];

    const int o2 = tid & 127;
    const int k  = o2 >> 5;
    const int o  = o2 & 31;
    const int vs = tid >> 7;
    uint2* yk = (k == 0) ? y0 : (k == 1) ? y1 : (k == 2) ? y2 : y3;
    const float* wk = sW + k * 64 * 32;

    for (int it = 0; it < ITER; it++) {
        const int v0 = (blockIdx.x * ITER + it) * 2;
        __syncthreads();
        for (int i = tid; i < 2 * 32; i += 256) {
            int vsl = i >> 5, u = i & 31;
            int v = v0 + vsl;
            sX[i] = (v < VN) ? x[v * 32 + u] : make_uint4(0u, 0u, 0u, 0u);
        }
        __syncthreads();

        int v = v0 + vs;
        if (v < VN) {
            float4 acc = make_float4(0.f, 0.f, 0.f, 0.f);
            const half2* xh = (const half2*)(sX + vs * 32);
#pragma unroll 8
            for (int c = 0; c < 64; c++) {
                float wv = wk[c * 32 + o];
                float2 a = __half22float2(xh[2 * c]);
                float2 b = __half22float2(xh[2 * c + 1]);
                acc.x += wv * a.x; acc.y += wv * a.y;
                acc.z += wv * b.x; acc.w += wv * b.y;
            }
            uint2 q;
            half2* h = (half2*)&q;
            h[0] = __floats2half2_rn(acc.x, acc.y);
            h[1] = __floats2half2_rn(acc.z, acc.w);
            yk[v * 32 + o] = q;
        }
    }
}

// ---------------- host orchestration ----------------
extern "C" void kernel_launch(void* const* d_in, const int* in_sizes, int n_in,
                              void* d_out, int out_size) {
    const float* x       = (const float*)d_in[0];
    const int*   ei      = (const int*)  d_in[1];
    const float* vals    = (const float*)d_in[2];
    const float* in_bn_g = (const float*)d_in[3];
    const float* in_bn_b = (const float*)d_in[4];
    const float* in_w    = (const float*)d_in[5];
    const float* in_b    = (const float*)d_in[6];
    const float* h0_bn_g = (const float*)d_in[7];
    const float* h0_bn_b = (const float*)d_in[8];
    const float* h0_w    = (const float*)d_in[9];
    const float* h0_b    = (const float*)d_in[10];
    const float* h1_bn_g = (const float*)d_in[11];
    const float* h1_bn_b = (const float*)d_in[12];
    const float* h1_w    = (const float*)d_in[13];
    const float* h1_b    = (const float*)d_in[14];
    float* out = (float*)d_out;

    const int* rows = ei;
    const int* cols = ei + EN;

    void *pXN, *pR1, *pSA, *pSB, *pSC, *pR0, *pWF, *pBF, *pWF2, *pQB2, *pPB2, *pQB1, *pQO;
    cudaGetSymbolAddress(&pXN, g_XN);
    cudaGetSymbolAddress(&pR1, g_R1);
    cudaGetSymbolAddress(&pSA, g_SA);
    cudaGetSymbolAddress(&pSB, g_SB);
    cudaGetSymbolAddress(&pSC, g_SC);
    cudaGetSymbolAddress(&pR0, g_R0);
    cudaGetSymbolAddress(&pWF, g_wf);
    cudaGetSymbolAddress(&pBF, g_bf);
    cudaGetSymbolAddress(&pWF2, g_wf2);
    cudaGetSymbolAddress(&pQB2, g_qb2);
    cudaGetSymbolAddress(&pPB2, g_pb2);
    cudaGetSymbolAddress(&pQB1, g_qb1);
    cudaGetSymbolAddress(&pQO,  g_qout);
    uint4* XN = (uint4*)pXN;
    uint4* R1 = (uint4*)pR1;
    uint4* SA = (uint4*)pSA;
    uint4* SB = (uint4*)pSB;
    uint4* SC = (uint4*)pSC;
    uint4* R0 = (uint4*)pR0;
    const float* WF  = (const float*)pWF;
    const float* BF  = (const float*)pBF;
    const float* WF2 = (const float*)pWF2;
    const float* QB2 = (const float*)pQB2;
    const float* PB2 = (const float*)pPB2;
    const float* QB1 = (const float*)pQB1;
    const float* QO  = (const float*)pQO;

    cudaFuncSetAttribute(k_combine<32, 64, 4>, cudaFuncAttributeMaxDynamicSharedMemorySize, 36864);
    cudaFuncSetAttribute(k_combine<64, 64, 4>, cudaFuncAttributeMaxDynamicSharedMemorySize, 73728);

    const int gG32 = (VN + 15) / 16;   // RU4=16 gather grid
    const int gG64 = (VN + 7) / 8;     // RU4=32 gather grid
    const int gCMB = (VN + 15) / 16;

    // ---- launches 1-3: CSR build + input BN, compressed ----
    k_hist_stats<<<G_HIST + G_RS + G_STAT, 256>>>(rows, x);
    k_scan<<<NB_SCAN + 1, 1024>>>();
    k_fill_apply<<<G_FILL + G_APPL + G_ZDEG, 256>>>(rows, cols, vals, x, in_bn_g, in_bn_b, (uint2*)pXN);

    // ---- layer 0: C=32 -> O=64 ----
    k_gather<16,0,0,0,0,0,0,0><<<gG32, 256>>>(1.f, XN, nullptr, 0.f, nullptr, 0.f, SA, nullptr, nullptr, nullptr, nullptr, nullptr);
    k_gather<16,0,1,0,0,0,0,0><<<gG32, 256>>>(2.f, SA, XN, -1.f, nullptr, 0.f, SB, nullptr, nullptr, nullptr, nullptr, nullptr);
    k_gather<16,0,1,0,0,0,0,0><<<gG32, 256>>>(2.f, SB, SA, -1.f, nullptr, 0.f, SC, nullptr, nullptr, nullptr, nullptr, nullptr);
    k_combine<32, 64, 4><<<gCMB, 256, 36864>>>(XN, SA, SB, SC, in_w, in_b, (uint2*)pR0);

    // ---- hidden-0 BN finalize + weight fold (fused) ----
    k_bn_fold1<<<1, 1024>>>(h0_bn_g, h0_bn_b, h0_w, h0_b);

    // ---- layer 1: C=64 -> O=64, single-pass gathers; x0 = affine(R0) on the fly ----
    k_gather<32,1,0,0,0,0,0,0><<<gG64, 256>>>(1.f, R0, nullptr, 0.f, nullptr, 0.f, SA, nullptr, nullptr, nullptr, nullptr, nullptr);
    k_gather<32,0,1,1,0,0,0,0><<<gG64, 256>>>(2.f, SA, R0, -1.f, nullptr, 0.f, SB, nullptr, nullptr, nullptr, nullptr, nullptr);
    k_gather<32,0,1,0,0,0,0,0><<<gG64, 256>>>(2.f, SB, SA, -1.f, nullptr, 0.f, SC, nullptr, nullptr, nullptr, nullptr, nullptr);
    k_combine<64, 64, 4><<<gCMB, 256, 73728>>>(R0, SA, SB, SC, WF, BF, (uint2*)pR1);

    // ---- hidden-1 BN finalize + weight fold + Clenshaw consts (fused) ----
    k_bn_fold2<<<1, 1024>>>(h1_bn_g, h1_bn_b, h1_w);

    // ---- layer 2 via Clenshaw on folded y^_k (width 32) ----
    k_combine4<8><<<(VN + 15) / 16, 256>>>(R1, WF2, (uint2*)pSA, (uint2*)pSB, (uint2*)pSC, (uint2*)pR0);
    // b2 = 2 L y^3 + y^2 + rs*(2u3) + u2   -> R1
    k_gather<16,0,1,0,0,1,1,0><<<gG32, 256>>>(2.f, R0, SC, 1.f, nullptr, 0.f, R1, QB2, PB2, nullptr, nullptr, nullptr);
    // b1 = 2 L b2 + y^1 - y^3 + (u1-u3)    -> SC
    k_gather<16,0,1,0,1,0,1,0><<<gG32, 256>>>(2.f, R1, SB, 1.f, R0, -1.f, SC, QB1, nullptr, nullptr, nullptr, nullptr);
    // out = relu(L b1 + y^0 - b2 + u0 + bias + xn), transposed to (B,32,V)
    k_gather<16,0,1,0,1,0,1,1><<<gG32, 256>>>(1.f, SC, SA, 1.f, R1, -1.f, nullptr, QO, nullptr, h1_b, XN, out);
}

// round 15
// speedup vs baseline: 1.0526x; 1.0526x over previous
#include <cuda_runtime.h>
#include <cuda_fp16.h>

#define VN 100000
#define EN 1600000
#define BATCH 4
#define BN_EPS 1e-5f
#define NB_SCAN 98            // ceil(VN/1024)
#define G_HIST 6250           // (EN+255)/256
#define G_RS   391            // (VN+255)/256
#define G_STAT 2048           // 32 channels x 64 blocks
#define G_FILL 6250
#define G_APPL 1563           // (VN+63)/64
#define G_ZDEG 391

// ---------------- static device scratch (no allocations allowed) ----------------
// feature tensors fp16, layout (V, C, B): element (v,c,b) at ((v*C+c)*4+b)
__device__ __align__(256) __half g_XN[VN * 32 * BATCH];   // BN'ed input (x0 of layer 0)
__device__ __align__(256) __half g_R1[VN * 64 * BATCH];   // relu(H1) / b2
__device__ __align__(256) __half g_SA[VN * 64 * BATCH];   // x1 / y0^
__device__ __align__(256) __half g_SB[VN * 64 * BATCH];   // x2 / y1^
__device__ __align__(256) __half g_SC[VN * 64 * BATCH];   // x3 / y2^ / b1
__device__ __align__(256) __half g_R0[VN * 64 * BATCH];   // relu(H0) / y3^
__device__ float g_red[128];
__device__ float g_scale[64];
__device__ float g_shift[64];

// folded weights / constant vectors
__device__ float g_wf[4 * 64 * 64];
__device__ float g_bf[64];
__device__ float g_wf2[4 * 64 * 32];
__device__ float g_qb2[32], g_pb2[32], g_qb1[32], g_qout[32];

// CSR scratch
__device__ __align__(256) int   g_deg[VN];
__device__ __align__(256) int   g_rowptr[VN + 1];
__device__ __align__(256) int   g_cursor[VN];
__device__ __align__(256) float g_rowsum[VN];
__device__ __align__(256) int   g_ecol[EN];
__device__ __align__(256) float g_eval[EN];

// decoupled-lookback scan state
__device__ volatile int g_agg[NB_SCAN];
__device__ volatile int g_incl[NB_SCAN];
__device__ volatile int g_flag[NB_SCAN];

// ---------------- fp16 helpers (8 values = 2 channels x 4 batch) ----------------
__device__ __forceinline__ void fma8(float* acc, float w, uint4 q) {
    half2* h = (half2*)&q;
#pragma unroll
    for (int t = 0; t < 4; t++) {
        float2 f = __half22float2(h[t]);
        acc[2 * t]     += w * f.x;
        acc[2 * t + 1] += w * f.y;
    }
}
__device__ __forceinline__ void unpack8(float* z, uint4 q) {
    half2* h = (half2*)&q;
#pragma unroll
    for (int t = 0; t < 4; t++) {
        float2 f = __half22float2(h[t]);
        z[2 * t] = f.x; z[2 * t + 1] = f.y;
    }
}
__device__ __forceinline__ uint4 pack8(const float* r) {
    uint4 q;
    half2* h = (half2*)&q;
#pragma unroll
    for (int t = 0; t < 4; t++) h[t] = __floats2half2_rn(r[2 * t], r[2 * t + 1]);
    return q;
}

// ================= launch 1: edge histogram + input BN stats + zero rowsum =================
__global__ void __launch_bounds__(256) k_hist_stats(const int* __restrict__ rows,
                                                    const float* __restrict__ x) {
    int b = blockIdx.x;
    if (b < G_HIST) {
        int e = b * 256 + threadIdx.x;
        if (e < EN) atomicAdd(&g_deg[rows[e]], 1);
        return;
    }
    b -= G_HIST;
    if (b < G_RS) {
        int i = b * 256 + threadIdx.x;
        if (i < VN) g_rowsum[i] = 0.f;
        return;
    }
    b -= G_RS;
    int c = b >> 6;
    int chunk = b & 63;
    float s1 = 0.f, s2 = 0.f;
    for (int v = chunk * 256 + threadIdx.x; v < VN; v += 64 * 256) {
#pragma unroll
        for (int bb = 0; bb < BATCH; bb++) {
            float t = x[(bb * 32 + c) * VN + v];
            s1 += t; s2 += t * t;
        }
    }
    __shared__ float sh1[256], sh2[256];
    sh1[threadIdx.x] = s1; sh2[threadIdx.x] = s2;
    __syncthreads();
    for (int off = 128; off > 0; off >>= 1) {
        if (threadIdx.x < off) {
            sh1[threadIdx.x] += sh1[threadIdx.x + off];
            sh2[threadIdx.x] += sh2[threadIdx.x + off];
        }
        __syncthreads();
    }
    if (threadIdx.x == 0) {
        atomicAdd(&g_red[c], sh1[0]);
        atomicAdd(&g_red[64 + c], sh2[0]);
    }
}

// ================= launch 2: decoupled-lookback scan + input BN finalize =================
__global__ void __launch_bounds__(1024) k_scan() {
    int b = blockIdx.x;
    int t = threadIdx.x;
    if (b == NB_SCAN) {
        __shared__ float sm[32], sv[32];
        if (t < 32) {
            float n = (float)VN * (float)BATCH;
            float m = g_red[t] / n;
            float var = g_red[64 + t] / n - m * m;
            sm[t] = m;
            sv[t] = rsqrtf(var + BN_EPS);
        }
        __syncthreads();
        if (t < 32) {
            g_scale[t] = sv[t];   // raw inv-std
            g_shift[t] = sm[t];   // raw mean
        }
        if (t < 128) g_red[t] = 0.f;
        if (t == 0) g_rowptr[VN] = EN;
        return;
    }
    __shared__ int sh[1024];
    int i = b * 1024 + t;
    int val = (i < VN) ? g_deg[i] : 0;
    sh[t] = val;
    __syncthreads();
    for (int off = 1; off < 1024; off <<= 1) {
        int tmp = (t >= off) ? sh[t - off] : 0;
        __syncthreads();
        sh[t] += tmp;
        __syncthreads();
    }
    __shared__ int s_prefix;
    if (t == 0) {
        int total = sh[1023];
        int prefix = 0;
        if (b == 0) {
            g_incl[0] = total;
            __threadfence();
            g_flag[0] = 2;
        } else {
            g_agg[b] = total;
            __threadfence();
            g_flag[b] = 1;
            int j = b - 1;
            while (true) {
                int f;
                while ((f = g_flag[j]) == 0) { }
                if (f == 2) { prefix += g_incl[j]; break; }
                prefix += g_agg[j];
                j--;
            }
            g_incl[b] = prefix + total;
            __threadfence();
            g_flag[b] = 2;
        }
        s_prefix = prefix;
    }
    __syncthreads();
    if (i < VN) {
        int excl = s_prefix + sh[t] - val;
        g_rowptr[i] = excl;
        g_cursor[i] = excl;
    }
}

// ================= launch 3: CSR fill + input BN apply/transpose + zero deg/flags =========
__global__ void __launch_bounds__(256) k_fill_apply(
        const int* __restrict__ rows, const int* __restrict__ cols,
        const float* __restrict__ vals, const float* __restrict__ x,
        const float* __restrict__ gam, const float* __restrict__ bet,
        uint2* __restrict__ xn) {
    int b = blockIdx.x;
    if (b < G_FILL) {
        int e = b * 256 + threadIdx.x;
        if (e < EN) {
            int r = rows[e];
            float w = vals[e];
            int pos = atomicAdd(&g_cursor[r], 1);
            g_ecol[pos] = cols[e];
            g_eval[pos] = w;
            atomicAdd(&g_rowsum[r], w);
        }
        return;
    }
    b -= G_FILL;
    if (b < G_APPL) {
        __shared__ uint2 tile[64 * 33];
        __shared__ float ssc[32], ssf[32];
        if (threadIdx.x < 32) {
            int c = threadIdx.x;
            float sc = gam[c] * g_scale[c];
            ssc[c] = sc;
            ssf[c] = bet[c] - g_shift[c] * sc;
        }
        __syncthreads();
        int v0 = b * 64;
        for (int i = threadIdx.x; i < 32 * 64; i += 256) {
            int c = i >> 6, vi = i & 63;
            int v = v0 + vi;
            uint2 q = make_uint2(0u, 0u);
            if (v < VN) {
                float sc = ssc[c], sf = ssf[c];
                float r0 = sc * x[(0 * 32 + c) * VN + v] + sf;
                float r1 = sc * x[(1 * 32 + c) * VN + v] + sf;
                float r2 = sc * x[(2 * 32 + c) * VN + v] + sf;
                float r3 = sc * x[(3 * 32 + c) * VN + v] + sf;
                half2* h = (half2*)&q;
                h[0] = __floats2half2_rn(r0, r1);
                h[1] = __floats2half2_rn(r2, r3);
            }
            tile[vi * 33 + c] = q;
        }
        __syncthreads();
        for (int i = threadIdx.x; i < 32 * 64; i += 256) {
            int vi = i >> 5, c = i & 31;
            int v = v0 + vi;
            if (v < VN) xn[v * 32 + c] = tile[vi * 33 + c];
        }
        return;
    }
    b -= G_APPL;
    int i = b * 256 + threadIdx.x;
    if (i < VN) g_deg[i] = 0;
    if (b == 0 && threadIdx.x < NB_SCAN) g_flag[threadIdx.x] = 0;
}

// ---------------- fused hidden-BN finalize + layer-1 weight fold (race-fixed) ---------------
__global__ void __launch_bounds__(1024) k_bn_fold1(
        const float* __restrict__ gam, const float* __restrict__ bet,
        const float* __restrict__ w, const float* __restrict__ bias) {
    int t = threadIdx.x;
    __shared__ float ssc[64], ssf[64];
    if (t < 64) {
        float n = (float)VN * (float)BATCH;
        float m = g_red[t] / n;
        float var = g_red[64 + t] / n - m * m;
        float sc = gam[t] * rsqrtf(var + BN_EPS);
        ssc[t] = sc;
        ssf[t] = bet[t] - m * sc;
    }
    __syncthreads();
    if (t < 64) { g_scale[t] = ssc[t]; g_shift[t] = ssf[t]; }
    if (t < 128) g_red[t] = 0.f;
    for (int i = t; i < 16384; i += 1024) {
        int k = i >> 12;
        int c = (i >> 6) & 63;
        float wv = w[i];
        g_wf[i] = (k == 0) ? wv * ssc[c] : wv;
    }
    if (t < 64) {
        float s = bias[t];
        for (int c = 0; c < 64; c++) s += w[c * 64 + t] * ssf[c];
        g_bf[t] = s;
    }
}

// ---------------- fused hidden-BN finalize + layer-2 weight fold + Clenshaw consts ---------
__global__ void __launch_bounds__(1024) k_bn_fold2(
        const float* __restrict__ gam, const float* __restrict__ bet,
        const float* __restrict__ w) {
    int t = threadIdx.x;
    __shared__ float ssc[64], ssf[64];
    __shared__ float su[4 * 32];
    if (t < 64) {
        float n = (float)VN * (float)BATCH;
        float m = g_red[t] / n;
        float var = g_red[64 + t] / n - m * m;
        float sc = gam[t] * rsqrtf(var + BN_EPS);
        ssc[t] = sc;
        ssf[t] = bet[t] - m * sc;
    }
    __syncthreads();
    if (t < 64) { g_scale[t] = ssc[t]; g_shift[t] = ssf[t]; }
    if (t < 128) g_red[t] = 0.f;
    for (int i = t; i < 8192; i += 1024) {
        int c = (i >> 5) & 63;
        g_wf2[i] = w[i] * ssc[c];
    }
    if (t < 128) {
        int k = t >> 5, o = t & 31;
        float u = 0.f;
        for (int c = 0; c < 64; c++) u += w[k * 2048 + c * 32 + o] * ssf[c];
        su[t] = u;
    }
    __syncthreads();
    if (t < 32) {
        g_qb2[t]  = su[2 * 32 + t];
        g_pb2[t]  = 2.f * su[3 * 32 + t];
        g_qb1[t]  = su[1 * 32 + t] - su[3 * 32 + t];
        g_qout[t] = su[0 * 32 + t];
    }
}

// ---------------- gather SpMM (R9 version): fp16, RU4 lanes per vertex ----------------
template<int RU4, bool AFFX, bool HASZ1, bool AFFZ1, bool HASZ2, bool HASP, bool HASQ, bool FINAL>
__global__ void __launch_bounds__(256) k_gather(
        float coef, const uint4* __restrict__ X,
        const uint4* __restrict__ Z1, float s1,
        const uint4* __restrict__ Z2, float s2,
        uint4* __restrict__ Y,
        const float* __restrict__ qv, const float* __restrict__ pv,
        const float* __restrict__ bias, const uint4* __restrict__ xn,
        float* __restrict__ outF) {
    const int VPB = 256 / RU4;
    int vs = threadIdx.x / RU4;
    int j  = threadIdx.x % RU4;
    int v  = blockIdx.x * VPB + vs;

    float r[8] = {0.f, 0.f, 0.f, 0.f, 0.f, 0.f, 0.f, 0.f};
    if (v < VN) {
        int s = g_rowptr[v];
        int e = g_rowptr[v + 1];
        float acc[8] = {0.f, 0.f, 0.f, 0.f, 0.f, 0.f, 0.f, 0.f};
        int i = s;
        for (; i < e && (i & 3); i++) {
            fma8(acc, __ldcs(&g_eval[i]), X[__ldcs(&g_ecol[i]) * RU4 + j]);
        }
        for (; i + 8 <= e; i += 8) {
            int4   ca = __ldcs((const int4*)&g_ecol[i]);
            int4   cb = __ldcs((const int4*)&g_ecol[i + 4]);
            float4 wa = __ldcs((const float4*)&g_eval[i]);
            float4 wb = __ldcs((const float4*)&g_eval[i + 4]);
            uint4 q0 = X[ca.x * RU4 + j];
            uint4 q1 = X[ca.y * RU4 + j];
            uint4 q2 = X[ca.z * RU4 + j];
            uint4 q3 = X[ca.w * RU4 + j];
            uint4 q4 = X[cb.x * RU4 + j];
            uint4 q5 = X[cb.y * RU4 + j];
            uint4 q6 = X[cb.z * RU4 + j];
            uint4 q7 = X[cb.w * RU4 + j];
            fma8(acc, wa.x, q0);
            fma8(acc, wa.y, q1);
            fma8(acc, wa.z, q2);
            fma8(acc, wa.w, q3);
            fma8(acc, wb.x, q4);
            fma8(acc, wb.y, q5);
            fma8(acc, wb.z, q6);
            fma8(acc, wb.w, q7);
        }
        for (; i + 4 <= e; i += 4) {
            int4   cc = __ldcs((const int4*)&g_ecol[i]);
            float4 ww = __ldcs((const float4*)&g_eval[i]);
            uint4 q0 = X[cc.x * RU4 + j];
            uint4 q1 = X[cc.y * RU4 + j];
            uint4 q2 = X[cc.z * RU4 + j];
            uint4 q3 = X[cc.w * RU4 + j];
            fma8(acc, ww.x, q0);
            fma8(acc, ww.y, q1);
            fma8(acc, ww.z, q2);
            fma8(acc, ww.w, q3);
        }
        for (; i < e; i++) {
            fma8(acc, __ldcs(&g_eval[i]), X[__ldcs(&g_ecol[i]) * RU4 + j]);
        }

        float sc0, sc1, sf0, sf1, rs = 0.f;
        if (AFFX || AFFZ1) {
            sc0 = g_scale[2 * j]; sc1 = g_scale[2 * j + 1];
            sf0 = g_shift[2 * j]; sf1 = g_shift[2 * j + 1];
        }
        if (AFFX || HASP) rs = g_rowsum[v];

        if (AFFX) {
#pragma unroll
            for (int b = 0; b < 4; b++) {
                r[b]     = coef * (sc0 * acc[b]     + sf0 * rs);
                r[4 + b] = coef * (sc1 * acc[4 + b] + sf1 * rs);
            }
        } else {
#pragma unroll
            for (int t = 0; t < 8; t++) r[t] = coef * acc[t];
        }
        if (HASZ1) {
            float z[8];
            unpack8(z, __ldcs(&Z1[v * RU4 + j]));
            if (AFFZ1) {
#pragma unroll
                for (int b = 0; b < 4; b++) {
                    r[b]     += s1 * (sc0 * z[b]     + sf0);
                    r[4 + b] += s1 * (sc1 * z[4 + b] + sf1);
                }
            } else {
#pragma unroll
                for (int t = 0; t < 8; t++) r[t] += s1 * z[t];
            }
        }
        if (HASZ2) {
            float z[8];
            unpack8(z, __ldcs(&Z2[v * RU4 + j]));
#pragma unroll
            for (int t = 0; t < 8; t++) r[t] += s2 * z[t];
        }
        if (HASQ) {
            float q0 = qv[2 * j], q1 = qv[2 * j + 1];
#pragma unroll
            for (int b = 0; b < 4; b++) { r[b] += q0; r[4 + b] += q1; }
        }
        if (HASP) {
            float p0 = pv[2 * j], p1 = pv[2 * j + 1];
#pragma unroll
            for (int b = 0; b < 4; b++) { r[b] += rs * p0; r[4 + b] += rs * p1; }
        }
        if (!FINAL) {
            __stcs(&Y[v * RU4 + j], pack8(r));
        }
    }

    if (FINAL) {
        // RU4 == 16, VPB == 16
        __shared__ float tile[16 * 32 * 4];
        if (v < VN) {
            float xr[8];
            unpack8(xr, xn[v * 16 + j]);
            float b0 = bias[2 * j], b1 = bias[2 * j + 1];
#pragma unroll
            for (int b = 0; b < 4; b++) {
                r[b]     = fmaxf(r[b]     + b0 + xr[b],     0.f);
                r[4 + b] = fmaxf(r[4 + b] + b1 + xr[4 + b], 0.f);
            }
        } else {
#pragma unroll
            for (int t = 0; t < 8; t++) r[t] = 0.f;
        }
#pragma unroll
        for (int b = 0; b < 4; b++) {
            tile[(vs * 32 + 2 * j) * 4 + b]     = r[b];
            tile[(vs * 32 + 2 * j + 1) * 4 + b] = r[4 + b];
        }
        __syncthreads();
        int vl = threadIdx.x & 15;
        int cw = threadIdx.x >> 4;
        int vv = blockIdx.x * 16 + vl;
        if (vv < VN) {
#pragma unroll
            for (int ci = 0; ci < 2; ci++) {
                int c = cw + ci * 16;
#pragma unroll
                for (int b = 0; b < 4; b++) {
                    outF[(b * 32 + c) * VN + vv] = tile[(vl * 32 + c) * 4 + b];
                }
            }
        }
    }
}

// ---------------- combine: fp16 smem, scalar FFMA; sW loaded as float4, high ITER ----------
// R[v,o,:] = relu(bias[o] + sum_kc w[kc,o]*xk[v,kc,:]) fp16 out; BN stats fused.
template<int C, int O, int ITER>
__global__ void __launch_bounds__(256) k_combine(
        const uint4* __restrict__ x0, const uint4* __restrict__ x1,
        const uint4* __restrict__ x2, const uint4* __restrict__ x3,
        const float* __restrict__ w, const float* __restrict__ bias,
        uint2* __restrict__ outR) {
    const int KC = 4 * C;
    const int RU = C / 2;
    const int VPB = 256 / O;
    extern __shared__ char smem[];
    float* sW = (float*)smem;
    uint4* sX = (uint4*)(smem + (size_t)KC * O * sizeof(float));
    __shared__ float sS1[64], sS2[64];
    const int tid = threadIdx.x;

    if (tid < O) { sS1[tid] = 0.f; sS2[tid] = 0.f; }
    // vectorized weight staging: KC*O floats as float4
    for (int i = tid; i < (KC * O) / 4; i += 256) {
        ((float4*)sW)[i] = ((const float4*)w)[i];
    }

    const int o = tid % O;
    const int vs = tid / O;
    const float bb = bias[o];
    float ls1 = 0.f, ls2 = 0.f;

    for (int it = 0; it < ITER; it++) {
        const int v0 = (blockIdx.x * ITER + it) * VPB;
        if (v0 >= VN) break;
        __syncthreads();
        for (int i = tid; i < VPB * 4 * RU; i += 256) {
            int vsl = i / (4 * RU);
            int rem = i - vsl * (4 * RU);
            int k = rem / RU, u = rem - k * RU;
            int v = v0 + vsl;
            const uint4* src = (k == 0) ? x0 : (k == 1) ? x1 : (k == 2) ? x2 : x3;
            sX[i] = (v < VN) ? src[v * RU + u] : make_uint4(0u, 0u, 0u, 0u);
        }
        __syncthreads();

        int v = v0 + vs;
        if (v < VN) {
            float4 acc = make_float4(bb, bb, bb, bb);
            const half2* xh = (const half2*)(sX + vs * 4 * RU);
#pragma unroll 8
            for (int kc = 0; kc < KC; kc++) {
                float wv = sW[kc * O + o];
                float2 a = __half22float2(xh[2 * kc]);
                float2 b = __half22float2(xh[2 * kc + 1]);
                acc.x += wv * a.x; acc.y += wv * a.y;
                acc.z += wv * b.x; acc.w += wv * b.y;
            }
            float a = fmaxf(acc.x, 0.f), b = fmaxf(acc.y, 0.f);
            float d = fmaxf(acc.z, 0.f), f = fmaxf(acc.w, 0.f);
            uint2 q;
            half2* h = (half2*)&q;
            h[0] = __floats2half2_rn(a, b);
            h[1] = __floats2half2_rn(d, f);
            outR[v * O + o] = q;
            ls1 += a + b + d + f;
            ls2 += a * a + b * b + d * d + f * f;
        }
    }

    atomicAdd(&sS1[o], ls1);
    atomicAdd(&sS2[o], ls2);
    __syncthreads();
    if (tid < O) {
        atomicAdd(&g_red[tid], sS1[tid]);
        atomicAdd(&g_red[64 + tid], sS2[tid]);
    }
}

// ---------------- combine4 (layer 2): y^_k = wf2_k^T R1; float4 sW staging, high ITER ------
template<int ITER>
__global__ void __launch_bounds__(256) k_combine4(
        const uint4* __restrict__ x, const float* __restrict__ w,
        uint2* __restrict__ y0, uint2* __restrict__ y1,
        uint2* __restrict__ y2, uint2* __restrict__ y3) {
    __shared__ float sW[4 * 64 * 32];
    __shared__ uint4 sX[2 * 32];
    const int tid = threadIdx.x;

    for (int i = tid; i < (4 * 64 * 32) / 4; i += 256) {
        ((float4*)sW)[i] = ((const float4*)w)[i];
    }

    const int o2 = tid & 127;
    const int k  = o2 >> 5;
    const int o  = o2 & 31;
    const int vs = tid >> 7;
    uint2* yk = (k == 0) ? y0 : (k == 1) ? y1 : (k == 2) ? y2 : y3;
    const float* wk = sW + k * 64 * 32;

    for (int it = 0; it < ITER; it++) {
        const int v0 = (blockIdx.x * ITER + it) * 2;
        if (v0 >= VN) break;
        __syncthreads();
        for (int i = tid; i < 2 * 32; i += 256) {
            int vsl = i >> 5, u = i & 31;
            int v = v0 + vsl;
            sX[i] = (v < VN) ? x[v * 32 + u] : make_uint4(0u, 0u, 0u, 0u);
        }
        __syncthreads();

        int v = v0 + vs;
        if (v < VN) {
            float4 acc = make_float4(0.f, 0.f, 0.f, 0.f);
            const half2* xh = (const half2*)(sX + vs * 32);
#pragma unroll 8
            for (int c = 0; c < 64; c++) {
                float wv = wk[c * 32 + o];
                float2 a = __half22float2(xh[2 * c]);
                float2 b = __half22float2(xh[2 * c + 1]);
                acc.x += wv * a.x; acc.y += wv * a.y;
                acc.z += wv * b.x; acc.w += wv * b.y;
            }
            uint2 q;
            half2* h = (half2*)&q;
            h[0] = __floats2half2_rn(acc.x, acc.y);
            h[1] = __floats2half2_rn(acc.z, acc.w);
            yk[v * 32 + o] = q;
        }
    }
}

// ---------------- host orchestration ----------------
extern "C" void kernel_launch(void* const* d_in, const int* in_sizes, int n_in,
                              void* d_out, int out_size) {
    const float* x       = (const float*)d_in[0];
    const int*   ei      = (const int*)  d_in[1];
    const float* vals    = (const float*)d_in[2];
    const float* in_bn_g = (const float*)d_in[3];
    const float* in_bn_b = (const float*)d_in[4];
    const float* in_w    = (const float*)d_in[5];
    const float* in_b    = (const float*)d_in[6];
    const float* h0_bn_g = (const float*)d_in[7];
    const float* h0_bn_b = (const float*)d_in[8];
    const float* h0_w    = (const float*)d_in[9];
    const float* h0_b    = (const float*)d_in[10];
    const float* h1_bn_g = (const float*)d_in[11];
    const float* h1_bn_b = (const float*)d_in[12];
    const float* h1_w    = (const float*)d_in[13];
    const float* h1_b    = (const float*)d_in[14];
    float* out = (float*)d_out;

    const int* rows = ei;
    const int* cols = ei + EN;

    void *pXN, *pR1, *pSA, *pSB, *pSC, *pR0, *pWF, *pBF, *pWF2, *pQB2, *pPB2, *pQB1, *pQO;
    cudaGetSymbolAddress(&pXN, g_XN);
    cudaGetSymbolAddress(&pR1, g_R1);
    cudaGetSymbolAddress(&pSA, g_SA);
    cudaGetSymbolAddress(&pSB, g_SB);
    cudaGetSymbolAddress(&pSC, g_SC);
    cudaGetSymbolAddress(&pR0, g_R0);
    cudaGetSymbolAddress(&pWF, g_wf);
    cudaGetSymbolAddress(&pBF, g_bf);
    cudaGetSymbolAddress(&pWF2, g_wf2);
    cudaGetSymbolAddress(&pQB2, g_qb2);
    cudaGetSymbolAddress(&pPB2, g_pb2);
    cudaGetSymbolAddress(&pQB1, g_qb1);
    cudaGetSymbolAddress(&pQO,  g_qout);
    uint4* XN = (uint4*)pXN;
    uint4* R1 = (uint4*)pR1;
    uint4* SA = (uint4*)pSA;
    uint4* SB = (uint4*)pSB;
    uint4* SC = (uint4*)pSC;
    uint4* R0 = (uint4*)pR0;
    const float* WF  = (const float*)pWF;
    const float* BF  = (const float*)pBF;
    const float* WF2 = (const float*)pWF2;
    const float* QB2 = (const float*)pQB2;
    const float* PB2 = (const float*)pPB2;
    const float* QB1 = (const float*)pQB1;
    const float* QO  = (const float*)pQO;

    cudaFuncSetAttribute(k_combine<32, 64, 16>, cudaFuncAttributeMaxDynamicSharedMemorySize, 36864);
    cudaFuncSetAttribute(k_combine<64, 64, 16>, cudaFuncAttributeMaxDynamicSharedMemorySize, 73728);

    const int gG32 = (VN + 15) / 16;    // RU4=16 gather grid
    const int gG64 = (VN + 7) / 8;      // RU4=32 gather grid
    const int gCMB = (VN + 63) / 64;    // combine grid: ITER=16 x VPB=4 vertices per block
    const int gCMB4 = (VN + 63) / 64;   // combine4 grid: ITER=32 x 2 vertices per block

    // ---- launches 1-3: CSR build + input BN, compressed ----
    k_hist_stats<<<G_HIST + G_RS + G_STAT, 256>>>(rows, x);
    k_scan<<<NB_SCAN + 1, 1024>>>();
    k_fill_apply<<<G_FILL + G_APPL + G_ZDEG, 256>>>(rows, cols, vals, x, in_bn_g, in_bn_b, (uint2*)pXN);

    // ---- layer 0: C=32 -> O=64 ----
    k_gather<16,0,0,0,0,0,0,0><<<gG32, 256>>>(1.f, XN, nullptr, 0.f, nullptr, 0.f, SA, nullptr, nullptr, nullptr, nullptr, nullptr);
    k_gather<16,0,1,0,0,0,0,0><<<gG32, 256>>>(2.f, SA, XN, -1.f, nullptr, 0.f, SB, nullptr, nullptr, nullptr, nullptr, nullptr);
    k_gather<16,0,1,0,0,0,0,0><<<gG32, 256>>>(2.f, SB, SA, -1.f, nullptr, 0.f, SC, nullptr, nullptr, nullptr, nullptr, nullptr);
    k_combine<32, 64, 16><<<gCMB, 256, 36864>>>(XN, SA, SB, SC, in_w, in_b, (uint2*)pR0);

    // ---- hidden-0 BN finalize + weight fold (fused) ----
    k_bn_fold1<<<1, 1024>>>(h0_bn_g, h0_bn_b, h0_w, h0_b);

    // ---- layer 1: C=64 -> O=64, single-pass gathers; x0 = affine(R0) on the fly ----
    k_gather<32,1,0,0,0,0,0,0><<<gG64, 256>>>(1.f, R0, nullptr, 0.f, nullptr, 0.f, SA, nullptr, nullptr, nullptr, nullptr, nullptr);
    k_gather<32,0,1,1,0,0,0,0><<<gG64, 256>>>(2.f, SA, R0, -1.f, nullptr, 0.f, SB, nullptr, nullptr, nullptr, nullptr, nullptr);
    k_gather<32,0,1,0,0,0,0,0><<<gG64, 256>>>(2.f, SB, SA, -1.f, nullptr, 0.f, SC, nullptr, nullptr, nullptr, nullptr, nullptr);
    k_combine<64, 64, 16><<<gCMB, 256, 73728>>>(R0, SA, SB, SC, WF, BF, (uint2*)pR1);

    // ---- hidden-1 BN finalize + weight fold + Clenshaw consts (fused) ----
    k_bn_fold2<<<1, 1024>>>(h1_bn_g, h1_bn_b, h1_w);

    // ---- layer 2 via Clenshaw on folded y^_k (width 32) ----
    k_combine4<32><<<gCMB4, 256>>>(R1, WF2, (uint2*)pSA, (uint2*)pSB, (uint2*)pSC, (uint2*)pR0);
    // b2 = 2 L y^3 + y^2 + rs*(2u3) + u2   -> R1
    k_gather<16,0,1,0,0,1,1,0><<<gG32, 256>>>(2.f, R0, SC, 1.f, nullptr, 0.f, R1, QB2, PB2, nullptr, nullptr, nullptr);
    // b1 = 2 L b2 + y^1 - y^3 + (u1-u3)    -> SC
    k_gather<16,0,1,0,1,0,1,0><<<gG32, 256>>>(2.f, R1, SB, 1.f, R0, -1.f, SC, QB1, nullptr, nullptr, nullptr, nullptr);
    // out = relu(L b1 + y^0 - b2 + u0 + bias + xn), transposed to (B,32,V)
    k_gather<16,0,1,0,1,0,1,1><<<gG32, 256>>>(1.f, SC, SA, 1.f, R1, -1.f, nullptr, QO, nullptr, h1_b, XN, out);
}

// round 16
// speedup vs baseline: 2.2224x; 2.1113x over previous
#include <cuda_runtime.h>
#include <cuda_fp16.h>

#define VN 100000
#define EN 1600000
#define BATCH 4
#define BN_EPS 1e-5f
#define NB_SCAN 98            // ceil(VN/1024)
#define G_HIST 6250           // (EN+255)/256
#define G_RS   391            // (VN+255)/256
#define G_STAT 2048           // 32 channels x 64 blocks
#define G_FILL 6250
#define G_APPL 1563           // (VN+63)/64
#define G_ZDEG 391
#define G_WCV  4              // in_w -> fp16 [o][kc] conversion blocks

// ---------------- static device scratch ----------------
__device__ __align__(256) __half g_XN[VN * 32 * BATCH];   // BN'ed input
__device__ __align__(256) __half g_R1[VN * 64 * BATCH];   // relu(H1) / b2
__device__ __align__(256) __half g_SA[VN * 64 * BATCH];   // x1 / y0^
__device__ __align__(256) __half g_SB[VN * 64 * BATCH];   // x2 / y1^
__device__ __align__(256) __half g_SC[VN * 64 * BATCH];   // x3 / y2^ / b1
__device__ __align__(256) __half g_R0[VN * 64 * BATCH];   // relu(H0) / y3^
__device__ float g_red[128];
__device__ float g_scale[64];
__device__ float g_shift[64];

// fp16 weights, [o][kc] layout (dense), + folded bias / Clenshaw consts
__device__ __align__(256) __half g_whf0[64 * 128];   // layer-0 W
__device__ __align__(256) __half g_whf1[64 * 256];   // layer-1 W (k=0 scaled)
__device__ __align__(256) __half g_whf2[128 * 64];   // layer-2 W, n=k*32+o
__device__ float g_bf[64];
__device__ float g_qb2[32], g_pb2[32], g_qb1[32], g_qout[32];

// CSR scratch
__device__ __align__(256) int   g_deg[VN];
__device__ __align__(256) int   g_rowptr[VN + 1];
__device__ __align__(256) int   g_cursor[VN];
__device__ __align__(256) float g_rowsum[VN];
__device__ __align__(256) int   g_ecol[EN];
__device__ __align__(256) float g_eval[EN];

// scan state
__device__ volatile int g_agg[NB_SCAN];
__device__ volatile int g_incl[NB_SCAN];
__device__ volatile int g_flag[NB_SCAN];

// ---------------- fp16 helpers ----------------
__device__ __forceinline__ void fma8(float* acc, float w, uint4 q) {
    half2* h = (half2*)&q;
#pragma unroll
    for (int t = 0; t < 4; t++) {
        float2 f = __half22float2(h[t]);
        acc[2 * t]     += w * f.x;
        acc[2 * t + 1] += w * f.y;
    }
}
__device__ __forceinline__ void unpack8(float* z, uint4 q) {
    half2* h = (half2*)&q;
#pragma unroll
    for (int t = 0; t < 4; t++) {
        float2 f = __half22float2(h[t]);
        z[2 * t] = f.x; z[2 * t + 1] = f.y;
    }
}
__device__ __forceinline__ uint4 pack8(const float* r) {
    uint4 q;
    half2* h = (half2*)&q;
#pragma unroll
    for (int t = 0; t < 4; t++) h[t] = __floats2half2_rn(r[2 * t], r[2 * t + 1]);
    return q;
}

__device__ __forceinline__ void mma16816(float* d, unsigned a0, unsigned a1,
                                         unsigned a2, unsigned a3,
                                         unsigned b0, unsigned b1) {
    asm volatile(
        "mma.sync.aligned.m16n8k16.row.col.f32.f16.f16.f32 "
        "{%0,%1,%2,%3}, {%4,%5,%6,%7}, {%8,%9}, {%0,%1,%2,%3};\n"
        : "+f"(d[0]), "+f"(d[1]), "+f"(d[2]), "+f"(d[3])
        : "r"(a0), "r"(a1), "r"(a2), "r"(a3), "r"(b0), "r"(b1));
}

// ================= launch 1: edge histogram + input BN stats + zero rowsum ================
__global__ void __launch_bounds__(256) k_hist_stats(const int* __restrict__ rows,
                                                    const float* __restrict__ x) {
    int b = blockIdx.x;
    if (b < G_HIST) {
        int e = b * 256 + threadIdx.x;
        if (e < EN) atomicAdd(&g_deg[rows[e]], 1);
        return;
    }
    b -= G_HIST;
    if (b < G_RS) {
        int i = b * 256 + threadIdx.x;
        if (i < VN) g_rowsum[i] = 0.f;
        return;
    }
    b -= G_RS;
    int c = b >> 6;
    int chunk = b & 63;
    float s1 = 0.f, s2 = 0.f;
    for (int v = chunk * 256 + threadIdx.x; v < VN; v += 64 * 256) {
#pragma unroll
        for (int bb = 0; bb < BATCH; bb++) {
            float t = x[(bb * 32 + c) * VN + v];
            s1 += t; s2 += t * t;
        }
    }
    __shared__ float sh1[256], sh2[256];
    sh1[threadIdx.x] = s1; sh2[threadIdx.x] = s2;
    __syncthreads();
    for (int off = 128; off > 0; off >>= 1) {
        if (threadIdx.x < off) {
            sh1[threadIdx.x] += sh1[threadIdx.x + off];
            sh2[threadIdx.x] += sh2[threadIdx.x + off];
        }
        __syncthreads();
    }
    if (threadIdx.x == 0) {
        atomicAdd(&g_red[c], sh1[0]);
        atomicAdd(&g_red[64 + c], sh2[0]);
    }
}

// ================= launch 2: decoupled-lookback scan + input BN finalize =================
__global__ void __launch_bounds__(1024) k_scan() {
    int b = blockIdx.x;
    int t = threadIdx.x;
    if (b == NB_SCAN) {
        __shared__ float sm[32], sv[32];
        if (t < 32) {
            float n = (float)VN * (float)BATCH;
            float m = g_red[t] / n;
            float var = g_red[64 + t] / n - m * m;
            sm[t] = m;
            sv[t] = rsqrtf(var + BN_EPS);
        }
        __syncthreads();
        if (t < 32) {
            g_scale[t] = sv[t];
            g_shift[t] = sm[t];
        }
        if (t < 128) g_red[t] = 0.f;
        if (t == 0) g_rowptr[VN] = EN;
        return;
    }
    __shared__ int sh[1024];
    int i = b * 1024 + t;
    int val = (i < VN) ? g_deg[i] : 0;
    sh[t] = val;
    __syncthreads();
    for (int off = 1; off < 1024; off <<= 1) {
        int tmp = (t >= off) ? sh[t - off] : 0;
        __syncthreads();
        sh[t] += tmp;
        __syncthreads();
    }
    __shared__ int s_prefix;
    if (t == 0) {
        int total = sh[1023];
        int prefix = 0;
        if (b == 0) {
            g_incl[0] = total;
            __threadfence();
            g_flag[0] = 2;
        } else {
            g_agg[b] = total;
            __threadfence();
            g_flag[b] = 1;
            int j = b - 1;
            while (true) {
                int f;
                while ((f = g_flag[j]) == 0) { }
                if (f == 2) { prefix += g_incl[j]; break; }
                prefix += g_agg[j];
                j--;
            }
            g_incl[b] = prefix + total;
            __threadfence();
            g_flag[b] = 2;
        }
        s_prefix = prefix;
    }
    __syncthreads();
    if (i < VN) {
        int excl = s_prefix + sh[t] - val;
        g_rowptr[i] = excl;
        g_cursor[i] = excl;
    }
}

// ====== launch 3: CSR fill + input BN apply/transpose + zero deg/flags + in_w->fp16 ======
__global__ void __launch_bounds__(256) k_fill_apply(
        const int* __restrict__ rows, const int* __restrict__ cols,
        const float* __restrict__ vals, const float* __restrict__ x,
        const float* __restrict__ gam, const float* __restrict__ bet,
        const float* __restrict__ in_w, uint2* __restrict__ xn) {
    int b = blockIdx.x;
    if (b < G_FILL) {
        int e = b * 256 + threadIdx.x;
        if (e < EN) {
            int r = rows[e];
            float w = vals[e];
            int pos = atomicAdd(&g_cursor[r], 1);
            g_ecol[pos] = cols[e];
            g_eval[pos] = w;
            atomicAdd(&g_rowsum[r], w);
        }
        return;
    }
    b -= G_FILL;
    if (b < G_APPL) {
        __shared__ uint2 tile[64 * 33];
        __shared__ float ssc[32], ssf[32];
        if (threadIdx.x < 32) {
            int c = threadIdx.x;
            float sc = gam[c] * g_scale[c];
            ssc[c] = sc;
            ssf[c] = bet[c] - g_shift[c] * sc;
        }
        __syncthreads();
        int v0 = b * 64;
        for (int i = threadIdx.x; i < 32 * 64; i += 256) {
            int c = i >> 6, vi = i & 63;
            int v = v0 + vi;
            uint2 q = make_uint2(0u, 0u);
            if (v < VN) {
                float sc = ssc[c], sf = ssf[c];
                float r0 = sc * x[(0 * 32 + c) * VN + v] + sf;
                float r1 = sc * x[(1 * 32 + c) * VN + v] + sf;
                float r2 = sc * x[(2 * 32 + c) * VN + v] + sf;
                float r3 = sc * x[(3 * 32 + c) * VN + v] + sf;
                half2* h = (half2*)&q;
                h[0] = __floats2half2_rn(r0, r1);
                h[1] = __floats2half2_rn(r2, r3);
            }
            tile[vi * 33 + c] = q;
        }
        __syncthreads();
        for (int i = threadIdx.x; i < 32 * 64; i += 256) {
            int vi = i >> 5, c = i & 31;
            int v = v0 + vi;
            if (v < VN) xn[v * 32 + c] = tile[vi * 33 + c];
        }
        return;
    }
    b -= G_APPL;
    if (b < G_ZDEG) {
        int i = b * 256 + threadIdx.x;
        if (i < VN) g_deg[i] = 0;
        if (b == 0 && threadIdx.x < NB_SCAN) g_flag[threadIdx.x] = 0;
        return;
    }
    b -= G_ZDEG;
    // convert in_w (4,32,64) -> g_whf0 [o][kc], kc = k*32+c
    for (int idx = b * 256 + threadIdx.x; idx < 64 * 128; idx += G_WCV * 256) {
        int o = idx >> 7;
        int kc = idx & 127;
        int k = kc >> 5, c = kc & 31;
        g_whf0[idx] = __float2half(in_w[k * 2048 + c * 64 + o]);
    }
}

// ---------------- fused hidden-BN finalize + layer-1 fp16 weight fold ----------------
__global__ void __launch_bounds__(1024) k_bn_fold1(
        const float* __restrict__ gam, const float* __restrict__ bet,
        const float* __restrict__ w, const float* __restrict__ bias) {
    int t = threadIdx.x;
    __shared__ float ssc[64], ssf[64];
    if (t < 64) {
        float n = (float)VN * (float)BATCH;
        float m = g_red[t] / n;
        float var = g_red[64 + t] / n - m * m;
        float sc = gam[t] * rsqrtf(var + BN_EPS);
        ssc[t] = sc;
        ssf[t] = bet[t] - m * sc;
    }
    __syncthreads();
    if (t < 64) { g_scale[t] = ssc[t]; g_shift[t] = ssf[t]; }
    if (t < 128) g_red[t] = 0.f;
    // g_whf1[o][kc], kc = k*64+c; w shape (4,64,64): idx = k*4096 + c*64 + o
    for (int idx = t; idx < 64 * 256; idx += 1024) {
        int o = idx >> 8;
        int kc = idx & 255;
        int k = kc >> 6, c = kc & 63;
        float wv = w[k * 4096 + c * 64 + o];
        if (k == 0) wv *= ssc[c];
        g_whf1[idx] = __float2half(wv);
    }
    if (t < 64) {
        float s = bias[t];
        for (int c = 0; c < 64; c++) s += w[c * 64 + t] * ssf[c];
        g_bf[t] = s;
    }
}

// ---------------- fused hidden-BN finalize + layer-2 fp16 fold + Clenshaw consts ----------
__global__ void __launch_bounds__(1024) k_bn_fold2(
        const float* __restrict__ gam, const float* __restrict__ bet,
        const float* __restrict__ w) {
    int t = threadIdx.x;
    __shared__ float ssc[64], ssf[64];
    __shared__ float su[4 * 32];
    if (t < 64) {
        float n = (float)VN * (float)BATCH;
        float m = g_red[t] / n;
        float var = g_red[64 + t] / n - m * m;
        float sc = gam[t] * rsqrtf(var + BN_EPS);
        ssc[t] = sc;
        ssf[t] = bet[t] - m * sc;
    }
    __syncthreads();
    if (t < 64) { g_scale[t] = ssc[t]; g_shift[t] = ssf[t]; }
    if (t < 128) g_red[t] = 0.f;
    // g_whf2[n][c], n = k*32+o; w shape (4,64,32): idx = k*2048 + c*32 + o
    for (int idx = t; idx < 128 * 64; idx += 1024) {
        int n = idx >> 6;
        int c = idx & 63;
        int k = n >> 5, o = n & 31;
        g_whf2[idx] = __float2half(w[k * 2048 + c * 32 + o] * ssc[c]);
    }
    if (t < 128) {
        int k = t >> 5, o = t & 31;
        float u = 0.f;
        for (int c = 0; c < 64; c++) u += w[k * 2048 + c * 32 + o] * ssf[c];
        su[t] = u;
    }
    __syncthreads();
    if (t < 32) {
        g_qb2[t]  = su[2 * 32 + t];
        g_pb2[t]  = 2.f * su[3 * 32 + t];
        g_qb1[t]  = su[1 * 32 + t] - su[3 * 32 + t];
        g_qout[t] = su[0 * 32 + t];
    }
}

// ---------------- gather SpMM (R9 version, unchanged) ----------------
template<int RU4, bool AFFX, bool HASZ1, bool AFFZ1, bool HASZ2, bool HASP, bool HASQ, bool FINAL>
__global__ void __launch_bounds__(256) k_gather(
        float coef, const uint4* __restrict__ X,
        const uint4* __restrict__ Z1, float s1,
        const uint4* __restrict__ Z2, float s2,
        uint4* __restrict__ Y,
        const float* __restrict__ qv, const float* __restrict__ pv,
        const float* __restrict__ bias, const uint4* __restrict__ xn,
        float* __restrict__ outF) {
    const int VPB = 256 / RU4;
    int vs = threadIdx.x / RU4;
    int j  = threadIdx.x % RU4;
    int v  = blockIdx.x * VPB + vs;

    float r[8] = {0.f, 0.f, 0.f, 0.f, 0.f, 0.f, 0.f, 0.f};
    if (v < VN) {
        int s = g_rowptr[v];
        int e = g_rowptr[v + 1];
        float acc[8] = {0.f, 0.f, 0.f, 0.f, 0.f, 0.f, 0.f, 0.f};
        int i = s;
        for (; i < e && (i & 3); i++) {
            fma8(acc, __ldcs(&g_eval[i]), X[__ldcs(&g_ecol[i]) * RU4 + j]);
        }
        for (; i + 8 <= e; i += 8) {
            int4   ca = __ldcs((const int4*)&g_ecol[i]);
            int4   cb = __ldcs((const int4*)&g_ecol[i + 4]);
            float4 wa = __ldcs((const float4*)&g_eval[i]);
            float4 wb = __ldcs((const float4*)&g_eval[i + 4]);
            uint4 q0 = X[ca.x * RU4 + j];
            uint4 q1 = X[ca.y * RU4 + j];
            uint4 q2 = X[ca.z * RU4 + j];
            uint4 q3 = X[ca.w * RU4 + j];
            uint4 q4 = X[cb.x * RU4 + j];
            uint4 q5 = X[cb.y * RU4 + j];
            uint4 q6 = X[cb.z * RU4 + j];
            uint4 q7 = X[cb.w * RU4 + j];
            fma8(acc, wa.x, q0);
            fma8(acc, wa.y, q1);
            fma8(acc, wa.z, q2);
            fma8(acc, wa.w, q3);
            fma8(acc, wb.x, q4);
            fma8(acc, wb.y, q5);
            fma8(acc, wb.z, q6);
            fma8(acc, wb.w, q7);
        }
        for (; i + 4 <= e; i += 4) {
            int4   cc = __ldcs((const int4*)&g_ecol[i]);
            float4 ww = __ldcs((const float4*)&g_eval[i]);
            uint4 q0 = X[cc.x * RU4 + j];
            uint4 q1 = X[cc.y * RU4 + j];
            uint4 q2 = X[cc.z * RU4 + j];
            uint4 q3 = X[cc.w * RU4 + j];
            fma8(acc, ww.x, q0);
            fma8(acc, ww.y, q1);
            fma8(acc, ww.z, q2);
            fma8(acc, ww.w, q3);
        }
        for (; i < e; i++) {
            fma8(acc, __ldcs(&g_eval[i]), X[__ldcs(&g_ecol[i]) * RU4 + j]);
        }

        float sc0, sc1, sf0, sf1, rs = 0.f;
        if (AFFX || AFFZ1) {
            sc0 = g_scale[2 * j]; sc1 = g_scale[2 * j + 1];
            sf0 = g_shift[2 * j]; sf1 = g_shift[2 * j + 1];
        }
        if (AFFX || HASP) rs = g_rowsum[v];

        if (AFFX) {
#pragma unroll
            for (int b = 0; b < 4; b++) {
                r[b]     = coef * (sc0 * acc[b]     + sf0 * rs);
                r[4 + b] = coef * (sc1 * acc[4 + b] + sf1 * rs);
            }
        } else {
#pragma unroll
            for (int t = 0; t < 8; t++) r[t] = coef * acc[t];
        }
        if (HASZ1) {
            float z[8];
            unpack8(z, __ldcs(&Z1[v * RU4 + j]));
            if (AFFZ1) {
#pragma unroll
                for (int b = 0; b < 4; b++) {
                    r[b]     += s1 * (sc0 * z[b]     + sf0);
                    r[4 + b] += s1 * (sc1 * z[4 + b] + sf1);
                }
            } else {
#pragma unroll
                for (int t = 0; t < 8; t++) r[t] += s1 * z[t];
            }
        }
        if (HASZ2) {
            float z[8];
            unpack8(z, __ldcs(&Z2[v * RU4 + j]));
#pragma unroll
            for (int t = 0; t < 8; t++) r[t] += s2 * z[t];
        }
        if (HASQ) {
            float q0 = qv[2 * j], q1 = qv[2 * j + 1];
#pragma unroll
            for (int b = 0; b < 4; b++) { r[b] += q0; r[4 + b] += q1; }
        }
        if (HASP) {
            float p0 = pv[2 * j], p1 = pv[2 * j + 1];
#pragma unroll
            for (int b = 0; b < 4; b++) { r[b] += rs * p0; r[4 + b] += rs * p1; }
        }
        if (!FINAL) {
            __stcs(&Y[v * RU4 + j], pack8(r));
        }
    }

    if (FINAL) {
        __shared__ float tile[16 * 32 * 4];
        if (v < VN) {
            float xr[8];
            unpack8(xr, xn[v * 16 + j]);
            float b0 = bias[2 * j], b1 = bias[2 * j + 1];
#pragma unroll
            for (int b = 0; b < 4; b++) {
                r[b]     = fmaxf(r[b]     + b0 + xr[b],     0.f);
                r[4 + b] = fmaxf(r[4 + b] + b1 + xr[4 + b], 0.f);
            }
        } else {
#pragma unroll
            for (int t = 0; t < 8; t++) r[t] = 0.f;
        }
#pragma unroll
        for (int b = 0; b < 4; b++) {
            tile[(vs * 32 + 2 * j) * 4 + b]     = r[b];
            tile[(vs * 32 + 2 * j + 1) * 4 + b] = r[4 + b];
        }
        __syncthreads();
        int vl = threadIdx.x & 15;
        int cw = threadIdx.x >> 4;
        int vv = blockIdx.x * 16 + vl;
        if (vv < VN) {
#pragma unroll
            for (int ci = 0; ci < 2; ci++) {
                int c = cw + ci * 16;
#pragma unroll
                for (int b = 0; b < 4; b++) {
                    outF[(b * 32 + c) * VN + vv] = tile[(vl * 32 + c) * 4 + b];
                }
            }
        }
    }
}

// ---------------- MMA combine (layers 0,1): out fp16 relu, BN stats fused ----------------
// D[(v,b), o] = relu(bias[o] + sum_kc X[(v,b),kc] * W[kc,o]); KC = 4*C, N = 64.
// 8 warps: (m-tile 0/1) x (n-group of 16). VN % 8 == 0 so no bounds checks.
template<int KC, int ITER>
__global__ void __launch_bounds__(256) k_mma_combine(
        const uint4* __restrict__ x0, const uint4* __restrict__ x1,
        const uint4* __restrict__ x2, const uint4* __restrict__ x3,
        const __half* __restrict__ wh, const float* __restrict__ bias,
        __half* __restrict__ outR) {
    const int C  = KC / 4;
    const int RU = C / 2;           // uint4 per (v,k) row
    const int KCP = KC + 8;         // padded row stride (halves)
    extern __shared__ __half smemh[];
    __half* sA = smemh;             // 32 x KCP
    __half* sB = smemh + 32 * KCP;  // 64 x KCP
    __shared__ float sS1[64], sS2[64];
    const int tid = threadIdx.x;
    const int wid = tid >> 5;
    const int lane = tid & 31;
    const int gid = lane >> 2;
    const int tid4 = lane & 3;
    const int tm = wid & 1;
    const int nbase = (wid >> 1) * 16;
    const int rowbase = tm * 16;

    if (tid < 64) { sS1[tid] = 0.f; sS2[tid] = 0.f; }
    // stage B (dense [64][KC] -> padded)
    for (int idx = tid; idx < 64 * (KC / 8); idx += 256) {
        int row = idx / (KC / 8);
        int c8  = idx - row * (KC / 8);
        *(uint4*)&sB[row * KCP + c8 * 8] = ((const uint4*)wh)[idx];
    }

    float ls1[4] = {0.f, 0.f, 0.f, 0.f};
    float ls2[4] = {0.f, 0.f, 0.f, 0.f};
    float bv[4];
#pragma unroll
    for (int t = 0; t < 2; t++) {
        bv[2 * t]     = bias[nbase + t * 8 + 2 * tid4];
        bv[2 * t + 1] = bias[nbase + t * 8 + 2 * tid4 + 1];
    }

    for (int it = 0; it < ITER; it++) {
        const int v0 = (blockIdx.x * ITER + it) * 8;
        __syncthreads();
        // stage A: [vb][kc] halves; vb = vloc*4+b
        for (int idx = tid; idx < 8 * 4 * RU; idx += 256) {
            int vloc = idx / (4 * RU);
            int rem  = idx - vloc * (4 * RU);
            int k = rem / RU, u = rem - k * RU;
            const uint4* src = (k == 0) ? x0 : (k == 1) ? x1 : (k == 2) ? x2 : x3;
            uint4 q = src[(v0 + vloc) * RU + u];
            int kc0 = k * C + 2 * u;
            __half* base = sA + (vloc * 4) * KCP + kc0;
            *(unsigned*)(base)            = __byte_perm(q.x, q.z, 0x5410);
            *(unsigned*)(base + KCP)      = __byte_perm(q.x, q.z, 0x7632);
            *(unsigned*)(base + 2 * KCP)  = __byte_perm(q.y, q.w, 0x5410);
            *(unsigned*)(base + 3 * KCP)  = __byte_perm(q.y, q.w, 0x7632);
        }
        __syncthreads();

        float d[2][4];
#pragma unroll
        for (int t = 0; t < 2; t++)
#pragma unroll
            for (int i = 0; i < 4; i++) d[t][i] = 0.f;

        for (int kb = 0; kb < KC; kb += 16) {
            unsigned a0 = *(unsigned*)&sA[(rowbase + gid) * KCP + kb + 2 * tid4];
            unsigned a1 = *(unsigned*)&sA[(rowbase + gid + 8) * KCP + kb + 2 * tid4];
            unsigned a2 = *(unsigned*)&sA[(rowbase + gid) * KCP + kb + 8 + 2 * tid4];
            unsigned a3 = *(unsigned*)&sA[(rowbase + gid + 8) * KCP + kb + 8 + 2 * tid4];
#pragma unroll
            for (int t = 0; t < 2; t++) {
                int o = nbase + t * 8 + gid;
                unsigned b0 = *(unsigned*)&sB[o * KCP + kb + 2 * tid4];
                unsigned b1 = *(unsigned*)&sB[o * KCP + kb + 8 + 2 * tid4];
                mma16816(d[t], a0, a1, a2, a3, b0, b1);
            }
        }

        // epilogue: bias + relu + store fp16 + stats
#pragma unroll
        for (int t = 0; t < 2; t++) {
            int c0 = nbase + t * 8 + 2 * tid4;
            int r0 = rowbase + gid;       // vb rows r0, r0+8
            float h00 = fmaxf(d[t][0] + bv[2 * t],     0.f);
            float h01 = fmaxf(d[t][1] + bv[2 * t + 1], 0.f);
            float h10 = fmaxf(d[t][2] + bv[2 * t],     0.f);
            float h11 = fmaxf(d[t][3] + bv[2 * t + 1], 0.f);
            ls1[2 * t]     += h00 + h10;
            ls2[2 * t]     += h00 * h00 + h10 * h10;
            ls1[2 * t + 1] += h01 + h11;
            ls2[2 * t + 1] += h01 * h01 + h11 * h11;
            int va = v0 + (r0 >> 2),      ba = r0 & 3;
            int vb2 = v0 + ((r0 + 8) >> 2), bb2 = (r0 + 8) & 3;
            outR[(va * 64 + c0) * 4 + ba]        = __float2half(h00);
            outR[(va * 64 + c0 + 1) * 4 + ba]    = __float2half(h01);
            outR[(vb2 * 64 + c0) * 4 + bb2]      = __float2half(h10);
            outR[(vb2 * 64 + c0 + 1) * 4 + bb2]  = __float2half(h11);
        }
    }

#pragma unroll
    for (int t = 0; t < 2; t++) {
        int c0 = nbase + t * 8 + 2 * tid4;
        atomicAdd(&sS1[c0], ls1[2 * t]);
        atomicAdd(&sS2[c0], ls2[2 * t]);
        atomicAdd(&sS1[c0 + 1], ls1[2 * t + 1]);
        atomicAdd(&sS2[c0 + 1], ls2[2 * t + 1]);
    }
    __syncthreads();
    if (tid < 64) {
        atomicAdd(&g_red[tid], sS1[tid]);
        atomicAdd(&g_red[64 + tid], sS2[tid]);
    }
}

// ---------------- MMA combine4 (layer 2): y^_n = R1 * W2 (N=128, K=64), fp16 out ----------
template<int ITER>
__global__ void __launch_bounds__(256) k_mma_combine4(
        const uint4* __restrict__ x, const __half* __restrict__ wh,
        __half* __restrict__ y0, __half* __restrict__ y1,
        __half* __restrict__ y2, __half* __restrict__ y3) {
    const int K = 64;
    const int KP = K + 8;
    extern __shared__ __half smemh[];
    __half* sA = smemh;             // 32 x KP
    __half* sB = smemh + 32 * KP;   // 128 x KP
    const int tid = threadIdx.x;
    const int wid = tid >> 5;
    const int lane = tid & 31;
    const int gid = lane >> 2;
    const int tid4 = lane & 3;
    const int tm = wid & 1;
    const int kg = wid >> 1;        // 0..3, selects W_k / output tensor
    const int rowbase = tm * 16;
    __half* yk = (kg == 0) ? y0 : (kg == 1) ? y1 : (kg == 2) ? y2 : y3;

    for (int idx = tid; idx < 128 * (K / 8); idx += 256) {
        int row = idx / (K / 8);
        int c8  = idx - row * (K / 8);
        *(uint4*)&sB[row * KP + c8 * 8] = ((const uint4*)wh)[idx];
    }

    for (int it = 0; it < ITER; it++) {
        const int v0 = (blockIdx.x * ITER + it) * 8;
        __syncthreads();
        for (int idx = tid; idx < 8 * 32; idx += 256) {   // RU=32 (C=64, single tensor)
            int vloc = idx >> 5;
            int u    = idx & 31;
            uint4 q = x[(v0 + vloc) * 32 + u];
            int kc0 = 2 * u;
            __half* base = sA + (vloc * 4) * KP + kc0;
            *(unsigned*)(base)           = __byte_perm(q.x, q.z, 0x5410);
            *(unsigned*)(base + KP)      = __byte_perm(q.x, q.z, 0x7632);
            *(unsigned*)(base + 2 * KP)  = __byte_perm(q.y, q.w, 0x5410);
            *(unsigned*)(base + 3 * KP)  = __byte_perm(q.y, q.w, 0x7632);
        }
        __syncthreads();

        float d[4][4];
#pragma unroll
        for (int t = 0; t < 4; t++)
#pragma unroll
            for (int i = 0; i < 4; i++) d[t][i] = 0.f;

        for (int kb = 0; kb < K; kb += 16) {
            unsigned a0 = *(unsigned*)&sA[(rowbase + gid) * KP + kb + 2 * tid4];
            unsigned a1 = *(unsigned*)&sA[(rowbase + gid + 8) * KP + kb + 2 * tid4];
            unsigned a2 = *(unsigned*)&sA[(rowbase + gid) * KP + kb + 8 + 2 * tid4];
            unsigned a3 = *(unsigned*)&sA[(rowbase + gid + 8) * KP + kb + 8 + 2 * tid4];
#pragma unroll
            for (int t = 0; t < 4; t++) {
                int n = kg * 32 + t * 8 + gid;
                unsigned b0 = *(unsigned*)&sB[n * KP + kb + 2 * tid4];
                unsigned b1 = *(unsigned*)&sB[n * KP + kb + 8 + 2 * tid4];
                mma16816(d[t], a0, a1, a2, a3, b0, b1);
            }
        }

#pragma unroll
        for (int t = 0; t < 4; t++) {
            int o0 = t * 8 + 2 * tid4;     // 0..31 within this k-group
            int r0 = rowbase + gid;
            int va = v0 + (r0 >> 2),        ba = r0 & 3;
            int vb2 = v0 + ((r0 + 8) >> 2), bb2 = (r0 + 8) & 3;
            yk[(va * 32 + o0) * 4 + ba]        = __float2half(d[t][0]);
            yk[(va * 32 + o0 + 1) * 4 + ba]    = __float2half(d[t][1]);
            yk[(vb2 * 32 + o0) * 4 + bb2]      = __float2half(d[t][2]);
            yk[(vb2 * 32 + o0 + 1) * 4 + bb2]  = __float2half(d[t][3]);
        }
    }
}

// ---------------- host orchestration ----------------
extern "C" void kernel_launch(void* const* d_in, const int* in_sizes, int n_in,
                              void* d_out, int out_size) {
    const float* x       = (const float*)d_in[0];
    const int*   ei      = (const int*)  d_in[1];
    const float* vals    = (const float*)d_in[2];
    const float* in_bn_g = (const float*)d_in[3];
    const float* in_bn_b = (const float*)d_in[4];
    const float* in_w    = (const float*)d_in[5];
    const float* in_b    = (const float*)d_in[6];
    const float* h0_bn_g = (const float*)d_in[7];
    const float* h0_bn_b = (const float*)d_in[8];
    const float* h0_w    = (const float*)d_in[9];
    const float* h0_b    = (const float*)d_in[10];
    const float* h1_bn_g = (const float*)d_in[11];
    const float* h1_bn_b = (const float*)d_in[12];
    const float* h1_w    = (const float*)d_in[13];
    const float* h1_b    = (const float*)d_in[14];
    float* out = (float*)d_out;

    const int* rows = ei;
    const int* cols = ei + EN;

    void *pXN, *pR1, *pSA, *pSB, *pSC, *pR0, *pW0, *pW1, *pW2, *pBF, *pQB2, *pPB2, *pQB1, *pQO;
    cudaGetSymbolAddress(&pXN, g_XN);
    cudaGetSymbolAddress(&pR1, g_R1);
    cudaGetSymbolAddress(&pSA, g_SA);
    cudaGetSymbolAddress(&pSB, g_SB);
    cudaGetSymbolAddress(&pSC, g_SC);
    cudaGetSymbolAddress(&pR0, g_R0);
    cudaGetSymbolAddress(&pW0, g_whf0);
    cudaGetSymbolAddress(&pW1, g_whf1);
    cudaGetSymbolAddress(&pW2, g_whf2);
    cudaGetSymbolAddress(&pBF, g_bf);
    cudaGetSymbolAddress(&pQB2, g_qb2);
    cudaGetSymbolAddress(&pPB2, g_pb2);
    cudaGetSymbolAddress(&pQB1, g_qb1);
    cudaGetSymbolAddress(&pQO,  g_qout);
    uint4* XN = (uint4*)pXN;
    uint4* R1 = (uint4*)pR1;
    uint4* SA = (uint4*)pSA;
    uint4* SB = (uint4*)pSB;
    uint4* SC = (uint4*)pSC;
    uint4* R0 = (uint4*)pR0;
    const __half* W0 = (const __half*)pW0;
    const __half* W1 = (const __half*)pW1;
    const __half* W2 = (const __half*)pW2;
    const float* BF  = (const float*)pBF;
    const float* QB2 = (const float*)pQB2;
    const float* PB2 = (const float*)pPB2;
    const float* QB1 = (const float*)pQB1;
    const float* QO  = (const float*)pQO;

    // dynamic smem: (32 + 64) * (KC+8) * 2 bytes for combine; (32+128)*(64+8)*2 for combine4
    cudaFuncSetAttribute(k_mma_combine<128, 5>, cudaFuncAttributeMaxDynamicSharedMemorySize, 96 * 136 * 2);
    cudaFuncSetAttribute(k_mma_combine<256, 5>, cudaFuncAttributeMaxDynamicSharedMemorySize, 96 * 264 * 2);
    cudaFuncSetAttribute(k_mma_combine4<5>,     cudaFuncAttributeMaxDynamicSharedMemorySize, 160 * 72 * 2);

    const int gG32 = (VN + 15) / 16;
    const int gG64 = (VN + 7) / 8;
    const int gMMA = 2500;   // 2500 blocks x ITER 5 x 8 vertices = 100000 exactly

    // ---- prologue ----
    k_hist_stats<<<G_HIST + G_RS + G_STAT, 256>>>(rows, x);
    k_scan<<<NB_SCAN + 1, 1024>>>();
    k_fill_apply<<<G_FILL + G_APPL + G_ZDEG + G_WCV, 256>>>(rows, cols, vals, x, in_bn_g, in_bn_b, in_w, (uint2*)pXN);

    // ---- layer 0: C=32 -> O=64 ----
    k_gather<16,0,0,0,0,0,0,0><<<gG32, 256>>>(1.f, XN, nullptr, 0.f, nullptr, 0.f, SA, nullptr, nullptr, nullptr, nullptr, nullptr);
    k_gather<16,0,1,0,0,0,0,0><<<gG32, 256>>>(2.f, SA, XN, -1.f, nullptr, 0.f, SB, nullptr, nullptr, nullptr, nullptr, nullptr);
    k_gather<16,0,1,0,0,0,0,0><<<gG32, 256>>>(2.f, SB, SA, -1.f, nullptr, 0.f, SC, nullptr, nullptr, nullptr, nullptr, nullptr);
    k_mma_combine<128, 5><<<gMMA, 256, 96 * 136 * 2>>>(XN, SA, SB, SC, W0, in_b, (__half*)pR0);

    // ---- hidden-0 BN finalize + fp16 weight fold ----
    k_bn_fold1<<<1, 1024>>>(h0_bn_g, h0_bn_b, h0_w, h0_b);

    // ---- layer 1: C=64 -> O=64 ----
    k_gather<32,1,0,0,0,0,0,0><<<gG64, 256>>>(1.f, R0, nullptr, 0.f, nullptr, 0.f, SA, nullptr, nullptr, nullptr, nullptr, nullptr);
    k_gather<32,0,1,1,0,0,0,0><<<gG64, 256>>>(2.f, SA, R0, -1.f, nullptr, 0.f, SB, nullptr, nullptr, nullptr, nullptr, nullptr);
    k_gather<32,0,1,0,0,0,0,0><<<gG64, 256>>>(2.f, SB, SA, -1.f, nullptr, 0.f, SC, nullptr, nullptr, nullptr, nullptr, nullptr);
    k_mma_combine<256, 5><<<gMMA, 256, 96 * 264 * 2>>>(R0, SA, SB, SC, W1, BF, (__half*)pR1);

    // ---- hidden-1 BN finalize + fp16 fold + Clenshaw consts ----
    k_bn_fold2<<<1, 1024>>>(h1_bn_g, h1_bn_b, h1_w);

    // ---- layer 2 via Clenshaw ----
    k_mma_combine4<5><<<gMMA, 256, 160 * 72 * 2>>>(R1, W2, (__half*)pSA, (__half*)pSB, (__half*)pSC, (__half*)pR0);
    // b2 = 2 L y^3 + y^2 + rs*(2u3) + u2   -> R1
    k_gather<16,0,1,0,0,1,1,0><<<gG32, 256>>>(2.f, R0, SC, 1.f, nullptr, 0.f, R1, QB2, PB2, nullptr, nullptr, nullptr);
    // b1 = 2 L b2 + y^1 - y^3 + (u1-u3)    -> SC
    k_gather<16,0,1,0,1,0,1,0><<<gG32, 256>>>(2.f, R1, SB, 1.f, R0, -1.f, SC, QB1, nullptr, nullptr, nullptr, nullptr);
    // out = relu(L b1 + y^0 - b2 + u0 + bias + xn), transposed to (B,32,V)
    k_gather<16,0,1,0,1,0,1,1><<<gG32, 256>>>(1.f, SC, SA, 1.f, R1, -1.f, nullptr, QO, nullptr, h1_b, XN, out);
}

// round 17
// speedup vs baseline: 2.2494x; 1.0122x over previous
#include <cuda_runtime.h>
#include <cuda_fp16.h>

#define VN 100000
#define EN 1600000
#define BATCH 4
#define BN_EPS 1e-5f
#define NB_SCAN 98            // ceil(VN/1024)
#define G_HIST 6250           // (EN+255)/256
#define G_RS   391            // (VN+255)/256
#define G_STAT 2048           // 32 channels x 64 blocks
#define G_FILL 6250
#define G_APPL 1563           // (VN+63)/64
#define G_ZDEG 391
#define G_WCV  4              // in_w -> fp16 [o][kc] conversion blocks

// ---------------- static device scratch ----------------
__device__ __align__(256) __half g_XN[VN * 32 * BATCH];   // BN'ed input
__device__ __align__(256) __half g_R1[VN * 64 * BATCH];   // relu(H1) / t1
__device__ __align__(256) __half g_SA[VN * 64 * BATCH];   // p1 / y'0
__device__ __align__(256) __half g_SB[VN * 64 * BATCH];   // p2 / y'1
__device__ __align__(256) __half g_SC[VN * 64 * BATCH];   // p3 / y'2 / t2
__device__ __align__(256) __half g_R0[VN * 64 * BATCH];   // relu(H0) / y'3
__device__ float g_red[128];
__device__ float g_scale[64];
__device__ float g_shift[64];

// fp16 weights, [o][kc] layout (dense), power-basis folded; bias/Horner consts
__device__ __align__(256) __half g_whf0[64 * 128];   // layer-0 W'
__device__ __align__(256) __half g_whf1[64 * 256];   // layer-1 W' (k=0 slice BN-scaled)
__device__ __align__(256) __half g_whf2[128 * 64];   // layer-2 W', n=k*32+o
__device__ float g_bf[64];
__device__ float g_u0[32], g_u1[32], g_u2[32], g_u3[32];   // Horner const vecs

// CSR scratch
__device__ __align__(256) int   g_deg[VN];
__device__ __align__(256) int   g_rowptr[VN + 1];
__device__ __align__(256) int   g_cursor[VN];
__device__ __align__(256) float g_rowsum[VN];
__device__ __align__(256) int   g_ecol[EN];
__device__ __align__(256) float g_eval[EN];

// scan state
__device__ volatile int g_agg[NB_SCAN];
__device__ volatile int g_incl[NB_SCAN];
__device__ volatile int g_flag[NB_SCAN];

// ---------------- fp16 helpers ----------------
__device__ __forceinline__ void fma8(float* acc, float w, uint4 q) {
    half2* h = (half2*)&q;
#pragma unroll
    for (int t = 0; t < 4; t++) {
        float2 f = __half22float2(h[t]);
        acc[2 * t]     += w * f.x;
        acc[2 * t + 1] += w * f.y;
    }
}
__device__ __forceinline__ void unpack8(float* z, uint4 q) {
    half2* h = (half2*)&q;
#pragma unroll
    for (int t = 0; t < 4; t++) {
        float2 f = __half22float2(h[t]);
        z[2 * t] = f.x; z[2 * t + 1] = f.y;
    }
}
__device__ __forceinline__ uint4 pack8(const float* r) {
    uint4 q;
    half2* h = (half2*)&q;
#pragma unroll
    for (int t = 0; t < 4; t++) h[t] = __floats2half2_rn(r[2 * t], r[2 * t + 1]);
    return q;
}

__device__ __forceinline__ void mma16816(float* d, unsigned a0, unsigned a1,
                                         unsigned a2, unsigned a3,
                                         unsigned b0, unsigned b1) {
    asm volatile(
        "mma.sync.aligned.m16n8k16.row.col.f32.f16.f16.f32 "
        "{%0,%1,%2,%3}, {%4,%5,%6,%7}, {%8,%9}, {%0,%1,%2,%3};\n"
        : "+f"(d[0]), "+f"(d[1]), "+f"(d[2]), "+f"(d[3])
        : "r"(a0), "r"(a1), "r"(a2), "r"(a3), "r"(b0), "r"(b1));
}

// ================= launch 1: edge histogram + input BN stats + zero rowsum ================
__global__ void __launch_bounds__(256) k_hist_stats(const int* __restrict__ rows,
                                                    const float* __restrict__ x) {
    int b = blockIdx.x;
    if (b < G_HIST) {
        int e = b * 256 + threadIdx.x;
        if (e < EN) atomicAdd(&g_deg[rows[e]], 1);
        return;
    }
    b -= G_HIST;
    if (b < G_RS) {
        int i = b * 256 + threadIdx.x;
        if (i < VN) g_rowsum[i] = 0.f;
        return;
    }
    b -= G_RS;
    int c = b >> 6;
    int chunk = b & 63;
    float s1 = 0.f, s2 = 0.f;
    for (int v = chunk * 256 + threadIdx.x; v < VN; v += 64 * 256) {
#pragma unroll
        for (int bb = 0; bb < BATCH; bb++) {
            float t = x[(bb * 32 + c) * VN + v];
            s1 += t; s2 += t * t;
        }
    }
    __shared__ float sh1[256], sh2[256];
    sh1[threadIdx.x] = s1; sh2[threadIdx.x] = s2;
    __syncthreads();
    for (int off = 128; off > 0; off >>= 1) {
        if (threadIdx.x < off) {
            sh1[threadIdx.x] += sh1[threadIdx.x + off];
            sh2[threadIdx.x] += sh2[threadIdx.x + off];
        }
        __syncthreads();
    }
    if (threadIdx.x == 0) {
        atomicAdd(&g_red[c], sh1[0]);
        atomicAdd(&g_red[64 + c], sh2[0]);
    }
}

// ================= launch 2: decoupled-lookback scan + input BN finalize =================
__global__ void __launch_bounds__(1024) k_scan() {
    int b = blockIdx.x;
    int t = threadIdx.x;
    if (b == NB_SCAN) {
        __shared__ float sm[32], sv[32];
        if (t < 32) {
            float n = (float)VN * (float)BATCH;
            float m = g_red[t] / n;
            float var = g_red[64 + t] / n - m * m;
            sm[t] = m;
            sv[t] = rsqrtf(var + BN_EPS);
        }
        __syncthreads();
        if (t < 32) {
            g_scale[t] = sv[t];
            g_shift[t] = sm[t];
        }
        if (t < 128) g_red[t] = 0.f;
        if (t == 0) g_rowptr[VN] = EN;
        return;
    }
    __shared__ int sh[1024];
    int i = b * 1024 + t;
    int val = (i < VN) ? g_deg[i] : 0;
    sh[t] = val;
    __syncthreads();
    for (int off = 1; off < 1024; off <<= 1) {
        int tmp = (t >= off) ? sh[t - off] : 0;
        __syncthreads();
        sh[t] += tmp;
        __syncthreads();
    }
    __shared__ int s_prefix;
    if (t == 0) {
        int total = sh[1023];
        int prefix = 0;
        if (b == 0) {
            g_incl[0] = total;
            __threadfence();
            g_flag[0] = 2;
        } else {
            g_agg[b] = total;
            __threadfence();
            g_flag[b] = 1;
            int j = b - 1;
            while (true) {
                int f;
                while ((f = g_flag[j]) == 0) { }
                if (f == 2) { prefix += g_incl[j]; break; }
                prefix += g_agg[j];
                j--;
            }
            g_incl[b] = prefix + total;
            __threadfence();
            g_flag[b] = 2;
        }
        s_prefix = prefix;
    }
    __syncthreads();
    if (i < VN) {
        int excl = s_prefix + sh[t] - val;
        g_rowptr[i] = excl;
        g_cursor[i] = excl;
    }
}

// ====== launch 3: CSR fill + input BN apply/transpose + zero deg/flags + in_w->fp16 ======
// in_w power-basis fold: w'0=w0-w2, w'1=w1-3w3, w'2=2w2, w'3=4w3.
__global__ void __launch_bounds__(256) k_fill_apply(
        const int* __restrict__ rows, const int* __restrict__ cols,
        const float* __restrict__ vals, const float* __restrict__ x,
        const float* __restrict__ gam, const float* __restrict__ bet,
        const float* __restrict__ in_w, uint2* __restrict__ xn) {
    int b = blockIdx.x;
    if (b < G_FILL) {
        int e = b * 256 + threadIdx.x;
        if (e < EN) {
            int r = rows[e];
            float w = vals[e];
            int pos = atomicAdd(&g_cursor[r], 1);
            g_ecol[pos] = cols[e];
            g_eval[pos] = w;
            atomicAdd(&g_rowsum[r], w);
        }
        return;
    }
    b -= G_FILL;
    if (b < G_APPL) {
        __shared__ uint2 tile[64 * 33];
        __shared__ float ssc[32], ssf[32];
        if (threadIdx.x < 32) {
            int c = threadIdx.x;
            float sc = gam[c] * g_scale[c];
            ssc[c] = sc;
            ssf[c] = bet[c] - g_shift[c] * sc;
        }
        __syncthreads();
        int v0 = b * 64;
        for (int i = threadIdx.x; i < 32 * 64; i += 256) {
            int c = i >> 6, vi = i & 63;
            int v = v0 + vi;
            uint2 q = make_uint2(0u, 0u);
            if (v < VN) {
                float sc = ssc[c], sf = ssf[c];
                float r0 = sc * x[(0 * 32 + c) * VN + v] + sf;
                float r1 = sc * x[(1 * 32 + c) * VN + v] + sf;
                float r2 = sc * x[(2 * 32 + c) * VN + v] + sf;
                float r3 = sc * x[(3 * 32 + c) * VN + v] + sf;
                half2* h = (half2*)&q;
                h[0] = __floats2half2_rn(r0, r1);
                h[1] = __floats2half2_rn(r2, r3);
            }
            tile[vi * 33 + c] = q;
        }
        __syncthreads();
        for (int i = threadIdx.x; i < 32 * 64; i += 256) {
            int vi = i >> 5, c = i & 31;
            int v = v0 + vi;
            if (v < VN) xn[v * 32 + c] = tile[vi * 33 + c];
        }
        return;
    }
    b -= G_APPL;
    if (b < G_ZDEG) {
        int i = b * 256 + threadIdx.x;
        if (i < VN) g_deg[i] = 0;
        if (b == 0 && threadIdx.x < NB_SCAN) g_flag[threadIdx.x] = 0;
        return;
    }
    b -= G_ZDEG;
    // in_w (4,32,64)[k][c][o] -> g_whf0[o][kc], power basis
    for (int idx = b * 256 + threadIdx.x; idx < 64 * 128; idx += G_WCV * 256) {
        int o = idx >> 7;
        int kc = idx & 127;
        int k = kc >> 5, c = kc & 31;
        float wv;
        if (k == 0)      wv = in_w[0 * 2048 + c * 64 + o] - in_w[2 * 2048 + c * 64 + o];
        else if (k == 1) wv = in_w[1 * 2048 + c * 64 + o] - 3.f * in_w[3 * 2048 + c * 64 + o];
        else if (k == 2) wv = 2.f * in_w[2 * 2048 + c * 64 + o];
        else             wv = 4.f * in_w[3 * 2048 + c * 64 + o];
        g_whf0[idx] = __float2half(wv);
    }
}

// ---------------- fused hidden-BN finalize + layer-1 fp16 power-basis fold ----------------
__global__ void __launch_bounds__(1024) k_bn_fold1(
        const float* __restrict__ gam, const float* __restrict__ bet,
        const float* __restrict__ w, const float* __restrict__ bias) {
    int t = threadIdx.x;
    __shared__ float ssc[64], ssf[64];
    if (t < 64) {
        float n = (float)VN * (float)BATCH;
        float m = g_red[t] / n;
        float var = g_red[64 + t] / n - m * m;
        float sc = gam[t] * rsqrtf(var + BN_EPS);
        ssc[t] = sc;
        ssf[t] = bet[t] - m * sc;
    }
    __syncthreads();
    if (t < 64) { g_scale[t] = ssc[t]; g_shift[t] = ssf[t]; }
    if (t < 128) g_red[t] = 0.f;
    // g_whf1[o][kc], kc=k*64+c; w (4,64,64): idx=k*4096+c*64+o; power basis; k=0 BN-scaled
    for (int idx = t; idx < 64 * 256; idx += 1024) {
        int o = idx >> 8;
        int kc = idx & 255;
        int k = kc >> 6, c = kc & 63;
        float wv;
        if (k == 0)      wv = (w[c * 64 + o] - w[2 * 4096 + c * 64 + o]) * ssc[c];
        else if (k == 1) wv = w[1 * 4096 + c * 64 + o] - 3.f * w[3 * 4096 + c * 64 + o];
        else if (k == 2) wv = 2.f * w[2 * 4096 + c * 64 + o];
        else             wv = 4.f * w[3 * 4096 + c * 64 + o];
        g_whf1[idx] = __float2half(wv);
    }
    if (t < 64) {
        float s = bias[t];
        for (int c = 0; c < 64; c++)
            s += (w[c * 64 + t] - w[2 * 4096 + c * 64 + t]) * ssf[c];
        g_bf[t] = s;
    }
}

// ---------------- fused hidden-BN finalize + layer-2 fp16 power fold + Horner consts ------
__global__ void __launch_bounds__(1024) k_bn_fold2(
        const float* __restrict__ gam, const float* __restrict__ bet,
        const float* __restrict__ w) {
    int t = threadIdx.x;
    __shared__ float ssc[64], ssf[64];
    __shared__ float su[4 * 32];
    if (t < 64) {
        float n = (float)VN * (float)BATCH;
        float m = g_red[t] / n;
        float var = g_red[64 + t] / n - m * m;
        float sc = gam[t] * rsqrtf(var + BN_EPS);
        ssc[t] = sc;
        ssf[t] = bet[t] - m * sc;
    }
    __syncthreads();
    if (t < 64) { g_scale[t] = ssc[t]; g_shift[t] = ssf[t]; }
    if (t < 128) g_red[t] = 0.f;
    // g_whf2[n][c], n=k*32+o; w (4,64,32): idx=k*2048+c*32+o; power basis W', BN-scaled
    for (int idx = t; idx < 128 * 64; idx += 1024) {
        int n = idx >> 6;
        int c = idx & 63;
        int k = n >> 5, o = n & 31;
        float wv;
        if (k == 0)      wv = w[c * 32 + o] - w[2 * 2048 + c * 32 + o];
        else if (k == 1) wv = w[1 * 2048 + c * 32 + o] - 3.f * w[3 * 2048 + c * 32 + o];
        else if (k == 2) wv = 2.f * w[2 * 2048 + c * 32 + o];
        else             wv = 4.f * w[3 * 2048 + c * 32 + o];
        g_whf2[idx] = __float2half(wv * ssc[c]);
    }
    // u'_k[o] = sum_c W'_k[c][o] * sf[c]
    if (t < 128) {
        int k = t >> 5, o = t & 31;
        float u = 0.f;
        for (int c = 0; c < 64; c++) {
            float wv;
            if (k == 0)      wv = w[c * 32 + o] - w[2 * 2048 + c * 32 + o];
            else if (k == 1) wv = w[1 * 2048 + c * 32 + o] - 3.f * w[3 * 2048 + c * 32 + o];
            else if (k == 2) wv = 2.f * w[2 * 2048 + c * 32 + o];
            else             wv = 4.f * w[3 * 2048 + c * 32 + o];
            u += wv * ssf[c];
        }
        su[t] = u;
    }
    __syncthreads();
    if (t < 32) {
        g_u0[t] = su[0 * 32 + t];
        g_u1[t] = su[1 * 32 + t];
        g_u2[t] = su[2 * 32 + t];
        g_u3[t] = su[3 * 32 + t];
    }
}

// ---------------- gather SpMM (R9/R16 version, unchanged) ----------------
template<int RU4, bool AFFX, bool HASZ1, bool AFFZ1, bool HASZ2, bool HASP, bool HASQ, bool FINAL>
__global__ void __launch_bounds__(256) k_gather(
        float coef, const uint4* __restrict__ X,
        const uint4* __restrict__ Z1, float s1,
        const uint4* __restrict__ Z2, float s2,
        uint4* __restrict__ Y,
        const float* __restrict__ qv, const float* __restrict__ pv,
        const float* __restrict__ bias, const uint4* __restrict__ xn,
        float* __restrict__ outF) {
    const int VPB = 256 / RU4;
    int vs = threadIdx.x / RU4;
    int j  = threadIdx.x % RU4;
    int v  = blockIdx.x * VPB + vs;

    float r[8] = {0.f, 0.f, 0.f, 0.f, 0.f, 0.f, 0.f, 0.f};
    if (v < VN) {
        int s = g_rowptr[v];
        int e = g_rowptr[v + 1];
        float acc[8] = {0.f, 0.f, 0.f, 0.f, 0.f, 0.f, 0.f, 0.f};
        int i = s;
        for (; i < e && (i & 3); i++) {
            fma8(acc, __ldcs(&g_eval[i]), X[__ldcs(&g_ecol[i]) * RU4 + j]);
        }
        for (; i + 8 <= e; i += 8) {
            int4   ca = __ldcs((const int4*)&g_ecol[i]);
            int4   cb = __ldcs((const int4*)&g_ecol[i + 4]);
            float4 wa = __ldcs((const float4*)&g_eval[i]);
            float4 wb = __ldcs((const float4*)&g_eval[i + 4]);
            uint4 q0 = X[ca.x * RU4 + j];
            uint4 q1 = X[ca.y * RU4 + j];
            uint4 q2 = X[ca.z * RU4 + j];
            uint4 q3 = X[ca.w * RU4 + j];
            uint4 q4 = X[cb.x * RU4 + j];
            uint4 q5 = X[cb.y * RU4 + j];
            uint4 q6 = X[cb.z * RU4 + j];
            uint4 q7 = X[cb.w * RU4 + j];
            fma8(acc, wa.x, q0);
            fma8(acc, wa.y, q1);
            fma8(acc, wa.z, q2);
            fma8(acc, wa.w, q3);
            fma8(acc, wb.x, q4);
            fma8(acc, wb.y, q5);
            fma8(acc, wb.z, q6);
            fma8(acc, wb.w, q7);
        }
        for (; i + 4 <= e; i += 4) {
            int4   cc = __ldcs((const int4*)&g_ecol[i]);
            float4 ww = __ldcs((const float4*)&g_eval[i]);
            uint4 q0 = X[cc.x * RU4 + j];
            uint4 q1 = X[cc.y * RU4 + j];
            uint4 q2 = X[cc.z * RU4 + j];
            uint4 q3 = X[cc.w * RU4 + j];
            fma8(acc, ww.x, q0);
            fma8(acc, ww.y, q1);
            fma8(acc, ww.z, q2);
            fma8(acc, ww.w, q3);
        }
        for (; i < e; i++) {
            fma8(acc, __ldcs(&g_eval[i]), X[__ldcs(&g_ecol[i]) * RU4 + j]);
        }

        float sc0, sc1, sf0, sf1, rs = 0.f;
        if (AFFX || AFFZ1) {
            sc0 = g_scale[2 * j]; sc1 = g_scale[2 * j + 1];
            sf0 = g_shift[2 * j]; sf1 = g_shift[2 * j + 1];
        }
        if (AFFX || HASP) rs = g_rowsum[v];

        if (AFFX) {
#pragma unroll
            for (int b = 0; b < 4; b++) {
                r[b]     = coef * (sc0 * acc[b]     + sf0 * rs);
                r[4 + b] = coef * (sc1 * acc[4 + b] + sf1 * rs);
            }
        } else {
#pragma unroll
            for (int t = 0; t < 8; t++) r[t] = coef * acc[t];
        }
        if (HASZ1) {
            float z[8];
            unpack8(z, __ldcs(&Z1[v * RU4 + j]));
            if (AFFZ1) {
#pragma unroll
                for (int b = 0; b < 4; b++) {
                    r[b]     += s1 * (sc0 * z[b]     + sf0);
                    r[4 + b] += s1 * (sc1 * z[4 + b] + sf1);
                }
            } else {
#pragma unroll
                for (int t = 0; t < 8; t++) r[t] += s1 * z[t];
            }
        }
        if (HASZ2) {
            float z[8];
            unpack8(z, __ldcs(&Z2[v * RU4 + j]));
#pragma unroll
            for (int t = 0; t < 8; t++) r[t] += s2 * z[t];
        }
        if (HASQ) {
            float q0 = qv[2 * j], q1 = qv[2 * j + 1];
#pragma unroll
            for (int b = 0; b < 4; b++) { r[b] += q0; r[4 + b] += q1; }
        }
        if (HASP) {
            float p0 = pv[2 * j], p1 = pv[2 * j + 1];
#pragma unroll
            for (int b = 0; b < 4; b++) { r[b] += rs * p0; r[4 + b] += rs * p1; }
        }
        if (!FINAL) {
            __stcs(&Y[v * RU4 + j], pack8(r));
        }
    }

    if (FINAL) {
        __shared__ float tile[16 * 32 * 4];
        if (v < VN) {
            float xr[8];
            unpack8(xr, xn[v * 16 + j]);
            float b0 = bias[2 * j], b1 = bias[2 * j + 1];
#pragma unroll
            for (int b = 0; b < 4; b++) {
                r[b]     = fmaxf(r[b]     + b0 + xr[b],     0.f);
                r[4 + b] = fmaxf(r[4 + b] + b1 + xr[4 + b], 0.f);
            }
        } else {
#pragma unroll
            for (int t = 0; t < 8; t++) r[t] = 0.f;
        }
#pragma unroll
        for (int b = 0; b < 4; b++) {
            tile[(vs * 32 + 2 * j) * 4 + b]     = r[b];
            tile[(vs * 32 + 2 * j + 1) * 4 + b] = r[4 + b];
        }
        __syncthreads();
        int vl = threadIdx.x & 15;
        int cw = threadIdx.x >> 4;
        int vv = blockIdx.x * 16 + vl;
        if (vv < VN) {
#pragma unroll
            for (int ci = 0; ci < 2; ci++) {
                int c = cw + ci * 16;
#pragma unroll
                for (int b = 0; b < 4; b++) {
                    outF[(b * 32 + c) * VN + vv] = tile[(vl * 32 + c) * 4 + b];
                }
            }
        }
    }
}

// ---------------- MMA combine (layers 0,1): out fp16 relu, BN stats fused ----------------
template<int KC, int ITER>
__global__ void __launch_bounds__(256) k_mma_combine(
        const uint4* __restrict__ x0, const uint4* __restrict__ x1,
        const uint4* __restrict__ x2, const uint4* __restrict__ x3,
        const __half* __restrict__ wh, const float* __restrict__ bias,
        __half* __restrict__ outR) {
    const int C  = KC / 4;
    const int RU = C / 2;
    const int KCP = KC + 8;
    extern __shared__ __half smemh[];
    __half* sA = smemh;             // 32 x KCP
    __half* sB = smemh + 32 * KCP;  // 64 x KCP
    __shared__ float sS1[64], sS2[64];
    const int tid = threadIdx.x;
    const int wid = tid >> 5;
    const int lane = tid & 31;
    const int gid = lane >> 2;
    const int tid4 = lane & 3;
    const int tm = wid & 1;
    const int nbase = (wid >> 1) * 16;
    const int rowbase = tm * 16;

    if (tid < 64) { sS1[tid] = 0.f; sS2[tid] = 0.f; }
    for (int idx = tid; idx < 64 * (KC / 8); idx += 256) {
        int row = idx / (KC / 8);
        int c8  = idx - row * (KC / 8);
        *(uint4*)&sB[row * KCP + c8 * 8] = ((const uint4*)wh)[idx];
    }

    float ls1[4] = {0.f, 0.f, 0.f, 0.f};
    float ls2[4] = {0.f, 0.f, 0.f, 0.f};
    float bv[4];
#pragma unroll
    for (int t = 0; t < 2; t++) {
        bv[2 * t]     = bias[nbase + t * 8 + 2 * tid4];
        bv[2 * t + 1] = bias[nbase + t * 8 + 2 * tid4 + 1];
    }

    for (int it = 0; it < ITER; it++) {
        const int v0 = (blockIdx.x * ITER + it) * 8;
        __syncthreads();
        for (int idx = tid; idx < 8 * 4 * RU; idx += 256) {
            int vloc = idx / (4 * RU);
            int rem  = idx - vloc * (4 * RU);
            int k = rem / RU, u = rem - k * RU;
            const uint4* src = (k == 0) ? x0 : (k == 1) ? x1 : (k == 2) ? x2 : x3;
            uint4 q = src[(v0 + vloc) * RU + u];
            int kc0 = k * C + 2 * u;
            __half* base = sA + (vloc * 4) * KCP + kc0;
            *(unsigned*)(base)            = __byte_perm(q.x, q.z, 0x5410);
            *(unsigned*)(base + KCP)      = __byte_perm(q.x, q.z, 0x7632);
            *(unsigned*)(base + 2 * KCP)  = __byte_perm(q.y, q.w, 0x5410);
            *(unsigned*)(base + 3 * KCP)  = __byte_perm(q.y, q.w, 0x7632);
        }
        __syncthreads();

        float d[2][4];
#pragma unroll
        for (int t = 0; t < 2; t++)
#pragma unroll
            for (int i = 0; i < 4; i++) d[t][i] = 0.f;

        for (int kb = 0; kb < KC; kb += 16) {
            unsigned a0 = *(unsigned*)&sA[(rowbase + gid) * KCP + kb + 2 * tid4];
            unsigned a1 = *(unsigned*)&sA[(rowbase + gid + 8) * KCP + kb + 2 * tid4];
            unsigned a2 = *(unsigned*)&sA[(rowbase + gid) * KCP + kb + 8 + 2 * tid4];
            unsigned a3 = *(unsigned*)&sA[(rowbase + gid + 8) * KCP + kb + 8 + 2 * tid4];
#pragma unroll
            for (int t = 0; t < 2; t++) {
                int o = nbase + t * 8 + gid;
                unsigned b0 = *(unsigned*)&sB[o * KCP + kb + 2 * tid4];
                unsigned b1 = *(unsigned*)&sB[o * KCP + kb + 8 + 2 * tid4];
                mma16816(d[t], a0, a1, a2, a3, b0, b1);
            }
        }

#pragma unroll
        for (int t = 0; t < 2; t++) {
            int c0 = nbase + t * 8 + 2 * tid4;
            int r0 = rowbase + gid;
            float h00 = fmaxf(d[t][0] + bv[2 * t],     0.f);
            float h01 = fmaxf(d[t][1] + bv[2 * t + 1], 0.f);
            float h10 = fmaxf(d[t][2] + bv[2 * t],     0.f);
            float h11 = fmaxf(d[t][3] + bv[2 * t + 1], 0.f);
            ls1[2 * t]     += h00 + h10;
            ls2[2 * t]     += h00 * h00 + h10 * h10;
            ls1[2 * t + 1] += h01 + h11;
            ls2[2 * t + 1] += h01 * h01 + h11 * h11;
            int va = v0 + (r0 >> 2),      ba = r0 & 3;
            int vb2 = v0 + ((r0 + 8) >> 2), bb2 = (r0 + 8) & 3;
            outR[(va * 64 + c0) * 4 + ba]        = __float2half(h00);
            outR[(va * 64 + c0 + 1) * 4 + ba]    = __float2half(h01);
            outR[(vb2 * 64 + c0) * 4 + bb2]      = __float2half(h10);
            outR[(vb2 * 64 + c0 + 1) * 4 + bb2]  = __float2half(h11);
        }
    }

#pragma unroll
    for (int t = 0; t < 2; t++) {
        int c0 = nbase + t * 8 + 2 * tid4;
        atomicAdd(&sS1[c0], ls1[2 * t]);
        atomicAdd(&sS2[c0], ls2[2 * t]);
        atomicAdd(&sS1[c0 + 1], ls1[2 * t + 1]);
        atomicAdd(&sS2[c0 + 1], ls2[2 * t + 1]);
    }
    __syncthreads();
    if (tid < 64) {
        atomicAdd(&g_red[tid], sS1[tid]);
        atomicAdd(&g_red[64 + tid], sS2[tid]);
    }
}

// ---------------- MMA combine4 (layer 2): y'_n = R1 * W2' (N=128, K=64), fp16 out ---------
template<int ITER>
__global__ void __launch_bounds__(256) k_mma_combine4(
        const uint4* __restrict__ x, const __half* __restrict__ wh,
        __half* __restrict__ y0, __half* __restrict__ y1,
        __half* __restrict__ y2, __half* __restrict__ y3) {
    const int K = 64;
    const int KP = K + 8;
    extern __shared__ __half smemh[];
    __half* sA = smemh;             // 32 x KP
    __half* sB = smemh + 32 * KP;   // 128 x KP
    const int tid = threadIdx.x;
    const int wid = tid >> 5;
    const int lane = tid & 31;
    const int gid = lane >> 2;
    const int tid4 = lane & 3;
    const int tm = wid & 1;
    const int kg = wid >> 1;
    const int rowbase = tm * 16;
    __half* yk = (kg == 0) ? y0 : (kg == 1) ? y1 : (kg == 2) ? y2 : y3;

    for (int idx = tid; idx < 128 * (K / 8); idx += 256) {
        int row = idx / (K / 8);
        int c8  = idx - row * (K / 8);
        *(uint4*)&sB[row * KP + c8 * 8] = ((const uint4*)wh)[idx];
    }

    for (int it = 0; it < ITER; it++) {
        const int v0 = (blockIdx.x * ITER + it) * 8;
        __syncthreads();
        for (int idx = tid; idx < 8 * 32; idx += 256) {
            int vloc = idx >> 5;
            int u    = idx & 31;
            uint4 q = x[(v0 + vloc) * 32 + u];
            int kc0 = 2 * u;
            __half* base = sA + (vloc * 4) * KP + kc0;
            *(unsigned*)(base)           = __byte_perm(q.x, q.z, 0x5410);
            *(unsigned*)(base + KP)      = __byte_perm(q.x, q.z, 0x7632);
            *(unsigned*)(base + 2 * KP)  = __byte_perm(q.y, q.w, 0x5410);
            *(unsigned*)(base + 3 * KP)  = __byte_perm(q.y, q.w, 0x7632);
        }
        __syncthreads();

        float d[4][4];
#pragma unroll
        for (int t = 0; t < 4; t++)
#pragma unroll
            for (int i = 0; i < 4; i++) d[t][i] = 0.f;

        for (int kb = 0; kb < K; kb += 16) {
            unsigned a0 = *(unsigned*)&sA[(rowbase + gid) * KP + kb + 2 * tid4];
            unsigned a1 = *(unsigned*)&sA[(rowbase + gid + 8) * KP + kb + 2 * tid4];
            unsigned a2 = *(unsigned*)&sA[(rowbase + gid) * KP + kb + 8 + 2 * tid4];
            unsigned a3 = *(unsigned*)&sA[(rowbase + gid + 8) * KP + kb + 8 + 2 * tid4];
#pragma unroll
            for (int t = 0; t < 4; t++) {
                int n = kg * 32 + t * 8 + gid;
                unsigned b0 = *(unsigned*)&sB[n * KP + kb + 2 * tid4];
                unsigned b1 = *(unsigned*)&sB[n * KP + kb + 8 + 2 * tid4];
                mma16816(d[t], a0, a1, a2, a3, b0, b1);
            }
        }

#pragma unroll
        for (int t = 0; t < 4; t++) {
            int o0 = t * 8 + 2 * tid4;
            int r0 = rowbase + gid;
            int va = v0 + (r0 >> 2),        ba = r0 & 3;
            int vb2 = v0 + ((r0 + 8) >> 2), bb2 = (r0 + 8) & 3;
            yk[(va * 32 + o0) * 4 + ba]        = __float2half(d[t][0]);
            yk[(va * 32 + o0 + 1) * 4 + ba]    = __float2half(d[t][1]);
            yk[(vb2 * 32 + o0) * 4 + bb2]      = __float2half(d[t][2]);
            yk[(vb2 * 32 + o0 + 1) * 4 + bb2]  = __float2half(d[t][3]);
        }
    }
}

// ---------------- host orchestration ----------------
extern "C" void kernel_launch(void* const* d_in, const int* in_sizes, int n_in,
                              void* d_out, int out_size) {
    const float* x       = (const float*)d_in[0];
    const int*   ei      = (const int*)  d_in[1];
    const float* vals    = (const float*)d_in[2];
    const float* in_bn_g = (const float*)d_in[3];
    const float* in_bn_b = (const float*)d_in[4];
    const float* in_w    = (const float*)d_in[5];
    const float* in_b    = (const float*)d_in[6];
    const float* h0_bn_g = (const float*)d_in[7];
    const float* h0_bn_b = (const float*)d_in[8];
    const float* h0_w    = (const float*)d_in[9];
    const float* h0_b    = (const float*)d_in[10];
    const float* h1_bn_g = (const float*)d_in[11];
    const float* h1_bn_b = (const float*)d_in[12];
    const float* h1_w    = (const float*)d_in[13];
    const float* h1_b    = (const float*)d_in[14];
    float* out = (float*)d_out;

    const int* rows = ei;
    const int* cols = ei + EN;

    void *pXN, *pR1, *pSA, *pSB, *pSC, *pR0, *pW0, *pW1, *pW2, *pBF, *pU0, *pU1, *pU2, *pU3;
    cudaGetSymbolAddress(&pXN, g_XN);
    cudaGetSymbolAddress(&pR1, g_R1);
    cudaGetSymbolAddress(&pSA, g_SA);
    cudaGetSymbolAddress(&pSB, g_SB);
    cudaGetSymbolAddress(&pSC, g_SC);
    cudaGetSymbolAddress(&pR0, g_R0);
    cudaGetSymbolAddress(&pW0, g_whf0);
    cudaGetSymbolAddress(&pW1, g_whf1);
    cudaGetSymbolAddress(&pW2, g_whf2);
    cudaGetSymbolAddress(&pBF, g_bf);
    cudaGetSymbolAddress(&pU0, g_u0);
    cudaGetSymbolAddress(&pU1, g_u1);
    cudaGetSymbolAddress(&pU2, g_u2);
    cudaGetSymbolAddress(&pU3, g_u3);
    uint4* XN = (uint4*)pXN;
    uint4* R1 = (uint4*)pR1;
    uint4* SA = (uint4*)pSA;
    uint4* SB = (uint4*)pSB;
    uint4* SC = (uint4*)pSC;
    uint4* R0 = (uint4*)pR0;
    const __half* W0 = (const __half*)pW0;
    const __half* W1 = (const __half*)pW1;
    const __half* W2 = (const __half*)pW2;
    const float* BF = (const float*)pBF;
    const float* U0 = (const float*)pU0;
    const float* U1 = (const float*)pU1;
    const float* U2 = (const float*)pU2;
    const float* U3 = (const float*)pU3;

    cudaFuncSetAttribute(k_mma_combine<128, 5>, cudaFuncAttributeMaxDynamicSharedMemorySize, 96 * 136 * 2);
    cudaFuncSetAttribute(k_mma_combine<256, 5>, cudaFuncAttributeMaxDynamicSharedMemorySize, 96 * 264 * 2);
    cudaFuncSetAttribute(k_mma_combine4<5>,     cudaFuncAttributeMaxDynamicSharedMemorySize, 160 * 72 * 2);

    const int gG32 = (VN + 15) / 16;
    const int gG64 = (VN + 7) / 8;
    const int gMMA = 2500;

    // ---- prologue ----
    k_hist_stats<<<G_HIST + G_RS + G_STAT, 256>>>(rows, x);
    k_scan<<<NB_SCAN + 1, 1024>>>();
    k_fill_apply<<<G_FILL + G_APPL + G_ZDEG + G_WCV, 256>>>(rows, cols, vals, x, in_bn_g, in_bn_b, in_w, (uint2*)pXN);

    // ---- layer 0: power basis p1,p2,p3 (no Z reads) ----
    k_gather<16,0,0,0,0,0,0,0><<<gG32, 256>>>(1.f, XN, nullptr, 0.f, nullptr, 0.f, SA, nullptr, nullptr, nullptr, nullptr, nullptr);
    k_gather<16,0,0,0,0,0,0,0><<<gG32, 256>>>(1.f, SA, nullptr, 0.f, nullptr, 0.f, SB, nullptr, nullptr, nullptr, nullptr, nullptr);
    k_gather<16,0,0,0,0,0,0,0><<<gG32, 256>>>(1.f, SB, nullptr, 0.f, nullptr, 0.f, SC, nullptr, nullptr, nullptr, nullptr, nullptr);
    k_mma_combine<128, 5><<<gMMA, 256, 96 * 136 * 2>>>(XN, SA, SB, SC, W0, in_b, (__half*)pR0);

    // ---- hidden-0 BN finalize + power-basis fp16 fold ----
    k_bn_fold1<<<1, 1024>>>(h0_bn_g, h0_bn_b, h0_w, h0_b);

    // ---- layer 1: p1 = L(affine(R0)), p2 = L p1, p3 = L p2 ----
    k_gather<32,1,0,0,0,0,0,0><<<gG64, 256>>>(1.f, R0, nullptr, 0.f, nullptr, 0.f, SA, nullptr, nullptr, nullptr, nullptr, nullptr);
    k_gather<32,0,0,0,0,0,0,0><<<gG64, 256>>>(1.f, SA, nullptr, 0.f, nullptr, 0.f, SB, nullptr, nullptr, nullptr, nullptr, nullptr);
    k_gather<32,0,0,0,0,0,0,0><<<gG64, 256>>>(1.f, SB, nullptr, 0.f, nullptr, 0.f, SC, nullptr, nullptr, nullptr, nullptr, nullptr);
    k_mma_combine<256, 5><<<gMMA, 256, 96 * 264 * 2>>>(R0, SA, SB, SC, W1, BF, (__half*)pR1);

    // ---- hidden-1 BN finalize + power fold + Horner consts ----
    k_bn_fold2<<<1, 1024>>>(h1_bn_g, h1_bn_b, h1_w);

    // ---- layer 2 via Horner: y'0=SA, y'1=SB, y'2=SC, y'3=R0 ----
    k_mma_combine4<5><<<gMMA, 256, 160 * 72 * 2>>>(R1, W2, (__half*)pSA, (__half*)pSB, (__half*)pSC, (__half*)pR0);
    // t1 = L y'3 + rowsum*u3 + y'2 + u2   -> R1
    k_gather<16,0,1,0,0,1,1,0><<<gG32, 256>>>(1.f, R0, SC, 1.f, nullptr, 0.f, R1, U2, U3, nullptr, nullptr, nullptr);
    // t2 = L t1 + y'1 + u1                -> SC
    k_gather<16,0,1,0,0,0,1,0><<<gG32, 256>>>(1.f, R1, SB, 1.f, nullptr, 0.f, SC, U1, nullptr, nullptr, nullptr, nullptr);
    // out = relu(L t2 + y'0 + u0 + bias + xn), transposed to (B,32,V)
    k_gather<16,0,1,0,0,0,1,1><<<gG32, 256>>>(1.f, SC, SA, 1.f, nullptr, 0.f, nullptr, U0, nullptr, h1_b, XN, out);
}